// round 7
// baseline (speedup 1.0000x reference)
#include <cuda_runtime.h>
#include <cuda_fp16.h>
#include <math.h>
#include <stdint.h>

#define S_LEN 4680
#define DIM 1536
#define NH 12
#define HD 128

// ---------------- static scratch ----------------
__device__ float  g_Q  [S_LEN*DIM];
__device__ float  g_K  [S_LEN*DIM];
__device__ float  g_XL [S_LEN*DIM];
__device__ float  g_Z  [S_LEN*NH];
__device__ float  g_WT [HD*HD];
__device__ __half g_xh [S_LEN*DIM];
__device__ __half g_Wqh[DIM*DIM];
__device__ __half g_Wkh[DIM*DIM];
__device__ __half g_Wvh[DIM*DIM];
__device__ __half g_Woh[DIM*DIM];
__device__ __half g_Vh [S_LEN*DIM];
__device__ __half g_RQh[S_LEN*DIM];
__device__ __half g_RKh[S_LEN*DIM];
__device__ __half g_XLh[S_LEN*DIM];
__device__ __half g_G2h[NH*HD*HD];   // [n][j][d]

// ---------------- helpers ----------------
__device__ __forceinline__ uint32_t pack_h2(float lo, float hi) {
    __half2 h = __floats2half2_rn(lo, hi);
    return *reinterpret_cast<uint32_t*>(&h);
}
__device__ __forceinline__ void mma_f16(float c[4],
                                        uint32_t a0, uint32_t a1, uint32_t a2, uint32_t a3,
                                        uint32_t b0, uint32_t b1) {
    asm("mma.sync.aligned.m16n8k16.row.col.f32.f16.f16.f32 "
        "{%0,%1,%2,%3},{%4,%5,%6,%7},{%8,%9},{%0,%1,%2,%3};"
        : "+f"(c[0]), "+f"(c[1]), "+f"(c[2]), "+f"(c[3])
        : "r"(a0), "r"(a1), "r"(a2), "r"(a3), "r"(b0), "r"(b1));
}
__device__ __forceinline__ void ldmx4(uint32_t &r0, uint32_t &r1, uint32_t &r2, uint32_t &r3,
                                      const __half* p) {
    uint32_t addr = (uint32_t)__cvta_generic_to_shared(p);
    asm volatile("ldmatrix.sync.aligned.m8n8.x4.shared.b16 {%0,%1,%2,%3},[%4];"
                 : "=r"(r0), "=r"(r1), "=r"(r2), "=r"(r3) : "r"(addr));
}
__device__ __forceinline__ void ldmx4t(uint32_t &r0, uint32_t &r1, uint32_t &r2, uint32_t &r3,
                                       const __half* p) {
    uint32_t addr = (uint32_t)__cvta_generic_to_shared(p);
    asm volatile("ldmatrix.sync.aligned.m8n8.x4.trans.shared.b16 {%0,%1,%2,%3},[%4];"
                 : "=r"(r0), "=r"(r1), "=r"(r2), "=r"(r3) : "r"(addr));
}
__device__ __forceinline__ void cp16(__half* dst, const __half* src, int src_bytes) {
    uint32_t d = (uint32_t)__cvta_generic_to_shared(dst);
    asm volatile("cp.async.cg.shared.global [%0], [%1], 16, %2;"
                 :: "r"(d), "l"(src), "r"(src_bytes));
}
#define CP_COMMIT() asm volatile("cp.async.commit_group;")
#define CP_WAIT1()  asm volatile("cp.async.wait_group 1;")

// ---------------- batched fp32 -> fp16 convert ----------------
__global__ void f2h_all_kernel(const float* __restrict__ x,
                               const float* __restrict__ w0, const float* __restrict__ w1,
                               const float* __restrict__ w2, const float* __restrict__ w3,
                               __half* __restrict__ xh,
                               __half* __restrict__ h0, __half* __restrict__ h1,
                               __half* __restrict__ h2, __half* __restrict__ h3) {
    const int NX = S_LEN * DIM / 4, NW = DIM * DIM / 4;
    const int total = NX + 4 * NW;
    for (int i = blockIdx.x * blockDim.x + threadIdx.x; i < total; i += gridDim.x * blockDim.x) {
        const float* src; __half* dst; int j = i;
        if (j < NX) { src = x; dst = xh; }
        else {
            j -= NX;
            int seg = j / NW; j -= seg * NW;
            src = (seg == 0) ? w0 : (seg == 1) ? w1 : (seg == 2) ? w2 : w3;
            dst = (seg == 0) ? h0 : (seg == 1) ? h1 : (seg == 2) ? h2 : h3;
        }
        float4 v = ((const float4*)src)[j];
        ((uint2*)dst)[j] = make_uint2(pack_h2(v.x, v.y), pack_h2(v.z, v.w));
    }
}

// ---------------- cp.async FP16 GEMM, 3-stage, ldmatrix ----------------
#define GKP 72
#define GSTG (2 * 128 * GKP)                  // halves per stage (A+B)
#define GEMM_SMEM (3 * GSTG * 2)              // bytes (~110.6KB)
template<bool HALF_OUT>
__global__ __launch_bounds__(256, 2) void gemm_async_kernel(
    const __half* __restrict__ A, const __half* __restrict__ W,
    const float* __restrict__ bias, void* __restrict__ Cout,
    int M, int N, int K) {
    extern __shared__ __half gsm[];
    const int tid = threadIdx.x;
    const int warp = tid >> 5, lane = tid & 31;
    const int g = lane >> 2, t = lane & 3;
    const int l15 = lane & 15, l16 = lane >> 4;
    const int wm = warp >> 2, wn = warp & 3;
    const int bm = blockIdx.y * 128, bn = blockIdx.x * 128;

    float acc[4][4][4];
#pragma unroll
    for (int i = 0; i < 4; i++)
#pragma unroll
        for (int j = 0; j < 4; j++)
#pragma unroll
            for (int r = 0; r < 4; r++) acc[i][j][r] = 0.f;

    auto load_stage = [&](int s, int k0) {
        __half* As = gsm + s * GSTG;
        __half* Bs = As + 128 * GKP;
#pragma unroll
        for (int it = 0; it < 4; it++) {
            int f = it * 256 + tid;
            int row = f >> 3, c8 = (f & 7) * 8;
            int gm = bm + row;
            const __half* sa = A + (size_t)(gm < M ? gm : M - 1) * K + k0 + c8;
            cp16(As + row * GKP + c8, sa, gm < M ? 16 : 0);
            const __half* sb = W + (size_t)(bn + row) * K + k0 + c8;
            cp16(Bs + row * GKP + c8, sb, 16);
        }
    };

    const int nT = K / 64;
    load_stage(0, 0);
    CP_COMMIT();
    load_stage(1, 64);
    CP_COMMIT();
    for (int i = 0; i < nT; i++) {
        CP_WAIT1();
        __syncthreads();
        if (i + 2 < nT) {
            int s = i + 2; while (s >= 3) s -= 3;
            load_stage(s, (i + 2) * 64);
            CP_COMMIT();
        } else {
            CP_COMMIT();   // keep group count advancing for wait_group 1
        }
        int cs = i; while (cs >= 3) cs -= 3;
        const __half* As = gsm + cs * GSTG;
        const __half* Bs = As + 128 * GKP;
#pragma unroll
        for (int ks = 0; ks < 4; ks++) {
            int kk = ks * 16;
            uint32_t af[4][4], bf[4][2];
#pragma unroll
            for (int mt = 0; mt < 4; mt++) {
                const __half* p = As + (wm * 64 + mt * 16 + l15) * GKP + kk + l16 * 8;
                ldmx4(af[mt][0], af[mt][1], af[mt][2], af[mt][3], p);
            }
#pragma unroll
            for (int np = 0; np < 2; np++) {
                const __half* p = Bs + (wn * 32 + np * 16 + l15) * GKP + kk + l16 * 8;
                ldmx4(bf[2*np][0], bf[2*np+1][0], bf[2*np][1], bf[2*np+1][1], p);
            }
#pragma unroll
            for (int mt = 0; mt < 4; mt++)
#pragma unroll
                for (int nt = 0; nt < 4; nt++)
                    mma_f16(acc[mt][nt], af[mt][0], af[mt][1], af[mt][2], af[mt][3],
                            bf[nt][0], bf[nt][1]);
        }
    }
#pragma unroll
    for (int mt = 0; mt < 4; mt++) {
#pragma unroll
        for (int nt = 0; nt < 4; nt++) {
            int col = bn + wn * 32 + nt * 8 + 2 * t;
            float2 b2 = *(const float2*)(bias + col);
            int r0 = bm + wm * 64 + mt * 16 + g;
            int r1 = r0 + 8;
            if (HALF_OUT) {
                __half* Ch = (__half*)Cout;
                if (r0 < M)
                    *(uint32_t*)(Ch + (size_t)r0 * N + col) =
                        pack_h2(acc[mt][nt][0] + b2.x, acc[mt][nt][1] + b2.y);
                if (r1 < M)
                    *(uint32_t*)(Ch + (size_t)r1 * N + col) =
                        pack_h2(acc[mt][nt][2] + b2.x, acc[mt][nt][3] + b2.y);
            } else {
                float* C = (float*)Cout;
                if (r0 < M)
                    *(float2*)(C + (size_t)r0 * N + col) =
                        make_float2(acc[mt][nt][0] + b2.x, acc[mt][nt][1] + b2.y);
                if (r1 < M)
                    *(float2*)(C + (size_t)r1 * N + col) =
                        make_float2(acc[mt][nt][2] + b2.x, acc[mt][nt][3] + b2.y);
            }
        }
    }
}

// ---------------- fused rmsnorm (+z) + rope -> fp16 ----------------
template<bool WITH_Z>
__global__ __launch_bounds__(384) void qkpost_kernel(
    const float* __restrict__ X, const float* __restrict__ gw,
    const float* __restrict__ gkm, const float* __restrict__ freqs,
    __half* __restrict__ Yh, float* __restrict__ Z) {
    __shared__ float vals[DIM];
    __shared__ float red[12];
    __shared__ float s_scale;
    const int s = blockIdx.x;
    const int tid = threadIdx.x;
    const int lane = tid & 31, wid = tid >> 5;
    const float* x = X + (size_t)s * DIM;

    float ss = 0.f;
#pragma unroll
    for (int k = 0; k < 4; k++) {
        int i = tid + k * 384;
        float v = x[i];
        vals[i] = v;
        ss += v * v;
    }
#pragma unroll
    for (int o = 16; o > 0; o >>= 1) ss += __shfl_xor_sync(0xffffffffu, ss, o);
    if (lane == 0) red[wid] = ss;
    __syncthreads();
    if (wid == 0) {
        float v = (lane < 12) ? red[lane] : 0.f;
#pragma unroll
        for (int o = 8; o > 0; o >>= 1) v += __shfl_xor_sync(0xffffffffu, v, o);
        if (lane == 0) s_scale = rsqrtf(v / (float)DIM + 1e-6f);
    }
    __syncthreads();
    const float sc = s_scale;
#pragma unroll
    for (int k = 0; k < 4; k++) {
        int i = tid + k * 384;
        vals[i] = vals[i] * sc * gw[i];
    }
    __syncthreads();
    if (WITH_Z) {
        const float* vh = vals + wid * HD;
        float sum = 0.f;
#pragma unroll
        for (int k = 0; k < 4; k++) {
            int d = lane + k * 32;
            sum += fmaxf(vh[d], 0.f) * gkm[wid * HD + d];
        }
#pragma unroll
        for (int o = 16; o > 0; o >>= 1) sum += __shfl_xor_sync(0xffffffffu, sum, o);
        if (lane == 0) Z[s * NH + wid] = 1.f / (sum + 1e-6f);
    }
    const int w = s % 52, h = (s / 52) % 30, f = s / (52 * 30);
#pragma unroll
    for (int k = 0; k < 2; k++) {
        int p = tid + k * 384;
        int i = p & 63;
        int pos = (i < 22) ? f : (i < 43) ? h : w;
        float cr = freqs[(pos * 64 + i) * 2 + 0];
        float ci = freqs[(pos * 64 + i) * 2 + 1];
        float xr = vals[2 * p], xi = vals[2 * p + 1];
        *(uint32_t*)(Yh + (size_t)s * DIM + 2 * p) =
            pack_h2(xr * cr - xi * ci, xr * ci + xi * cr);
    }
}

// ---------------- Wlin transpose ----------------
__global__ void transpose128_kernel(const float* __restrict__ in, float* __restrict__ out) {
    int j = blockIdx.x, m = threadIdx.x;
    out[m * HD + j] = in[j * HD + m];
}

// ---------------- G2h[n][j][d] ----------------
__global__ void g2_kernel(const float* __restrict__ gkv, const float* __restrict__ WT,
                          __half* __restrict__ G2h) {
    int nd = blockIdx.x;
    int n = nd >> 7, d = nd & 127;
    __shared__ float kv[HD];
    kv[threadIdx.x] = gkv[(size_t)nd * HD + threadIdx.x];
    __syncthreads();
    int j = threadIdx.x;
    float sum = 0.f;
#pragma unroll 8
    for (int m = 0; m < HD; m++) sum += kv[m] * WT[m * HD + j];
    G2h[((size_t)n * HD + j) * HD + d] = __float2half(sum);
}

// ---------------- xg via tensor cores ----------------
#define KPH 136
#define XG_SMEM (2 * 128 * KPH * 2)
__global__ __launch_bounds__(256) void xg_mma_kernel(
    const __half* __restrict__ RQh, const __half* __restrict__ G2h,
    const float* __restrict__ Z, const float* __restrict__ blin,
    const float* __restrict__ XL, __half* __restrict__ XLh) {
    extern __shared__ __half xsm[];
    __half* RQs = xsm;
    __half* G2s = xsm + 128 * KPH;
    const int tid = threadIdx.x;
    const int warp = tid >> 5, lane = tid & 31;
    const int g = lane >> 2, t = lane & 3;
    const int l15 = lane & 15, l16 = lane >> 4;
    const int head = blockIdx.y;
    const int q0 = blockIdx.x * 128;

#pragma unroll
    for (int it = 0; it < 8; it++) {
        int f = it * 256 + tid;
        int row = f >> 4, c8 = (f & 15) * 8;
        int s = q0 + row;
        uint4 v = make_uint4(0, 0, 0, 0);
        if (s < S_LEN) v = *(const uint4*)(RQh + ((size_t)s * NH + head) * HD + c8);
        *(uint4*)&RQs[row * KPH + c8] = v;
        uint4 gv = *(const uint4*)(G2h + ((size_t)head * HD + row) * HD + c8);
        *(uint4*)&G2s[row * KPH + c8] = gv;
    }
    __syncthreads();

    uint32_t qf[8][4];
#pragma unroll
    for (int kt = 0; kt < 8; kt++) {
        const __half* p = RQs + (warp * 16 + l15) * KPH + kt * 16 + l16 * 8;
        ldmx4(qf[kt][0], qf[kt][1], qf[kt][2], qf[kt][3], p);
    }
    float acc[16][4];
#pragma unroll
    for (int nt = 0; nt < 16; nt++)
#pragma unroll
        for (int r = 0; r < 4; r++) acc[nt][r] = 0.f;
#pragma unroll
    for (int kt = 0; kt < 8; kt++) {
#pragma unroll
        for (int np = 0; np < 8; np++) {
            uint32_t b00, b10, b01, b11;
            const __half* p = G2s + (np * 16 + l15) * KPH + kt * 16 + l16 * 8;
            ldmx4(b00, b10, b01, b11, p);
            mma_f16(acc[2*np    ], qf[kt][0], qf[kt][1], qf[kt][2], qf[kt][3], b00, b01);
            mma_f16(acc[2*np + 1], qf[kt][0], qf[kt][1], qf[kt][2], qf[kt][3], b10, b11);
        }
    }
    int s0r = q0 + warp * 16 + g;
    int s1r = s0r + 8;
    float z0 = (s0r < S_LEN) ? Z[s0r * NH + head] : 0.f;
    float z1 = (s1r < S_LEN) ? Z[s1r * NH + head] : 0.f;
#pragma unroll
    for (int nt = 0; nt < 16; nt++) {
        int col = nt * 8 + 2 * t;
        float2 bl = *(const float2*)(blin + col);
        if (s0r < S_LEN) {
            const float* xl = XL + ((size_t)s0r * NH + head) * HD + col;
            *(uint32_t*)(XLh + ((size_t)s0r * NH + head) * HD + col) =
                pack_h2(acc[nt][0] * z0 + bl.x + xl[0], acc[nt][1] * z0 + bl.y + xl[1]);
        }
        if (s1r < S_LEN) {
            const float* xl = XL + ((size_t)s1r * NH + head) * HD + col;
            *(uint32_t*)(XLh + ((size_t)s1r * NH + head) * HD + col) =
                pack_h2(acc[nt][2] * z1 + bl.x + xl[0], acc[nt][3] * z1 + bl.y + xl[1]);
        }
    }
}

// ---------------- FP16 flash attention, Bc=128, 3-stage, ldmatrix ----------------
#define ASTG (2 * 128 * KPH)            // halves per stage (K+V)
#define ATT_SMEM (3 * ASTG * 2)         // 3 stages (~209KB)
__global__ __launch_bounds__(256, 1) void attn_h_kernel(
    const __half* __restrict__ RQh, const __half* __restrict__ RKh,
    const __half* __restrict__ Vh, float* __restrict__ XL) {
    extern __shared__ __half smh[];
    const int tid = threadIdx.x;
    const int warp = tid >> 5, lane = tid & 31;
    const int g = lane >> 2, t = lane & 3;
    const int l15 = lane & 15, l16 = lane >> 4;
    const int head = blockIdx.y;
    const int q0 = blockIdx.x * 128;

    // stage Q in stage-2 region (loaded last into pipeline), read fragments
    {
        __half* Qs = smh + 2 * ASTG;
#pragma unroll
        for (int it = 0; it < 8; it++) {
            int f = it * 256 + tid;
            int row = f >> 4, c8 = (f & 15) * 8;
            int s = q0 + row;
            uint4 v = make_uint4(0, 0, 0, 0);
            if (s < S_LEN) v = *(const uint4*)(RQh + ((size_t)s * NH + head) * HD + c8);
            *(uint4*)&Qs[row * KPH + c8] = v;
        }
    }
    __syncthreads();
    uint32_t qf[8][4];
#pragma unroll
    for (int kt = 0; kt < 8; kt++) {
        const __half* p = smh + 2 * ASTG + (warp * 16 + l15) * KPH + kt * 16 + l16 * 8;
        ldmx4(qf[kt][0], qf[kt][1], qf[kt][2], qf[kt][3], p);
    }
    __syncthreads();   // Q reads done before stage-2 gets K/V

    auto load_kv = [&](int st, int k0) {
        __half* Ks = smh + st * ASTG;
        __half* Vs = Ks + 128 * KPH;
#pragma unroll
        for (int it = 0; it < 8; it++) {
            int f = it * 256 + tid;
            int row = f >> 4, c8 = (f & 15) * 8;
            int s = k0 + row;
            int sb = (s < S_LEN) ? 16 : 0;
            size_t off = ((size_t)(s < S_LEN ? s : S_LEN - 1) * NH + head) * HD + c8;
            cp16(Ks + row * KPH + c8, RKh + off, sb);
            cp16(Vs + row * KPH + c8, Vh + off, sb);
        }
    };

    float o_acc[16][4];
#pragma unroll
    for (int nt = 0; nt < 16; nt++)
#pragma unroll
        for (int r = 0; r < 4; r++) o_acc[nt][r] = 0.f;
    float m0 = -1e30f, m1 = -1e30f, l0 = 0.f, l1 = 0.f;
    const float scale = 0.08838834764831845f;
    const int T = (S_LEN + 127) / 128;

    load_kv(0, 0);
    CP_COMMIT();
    load_kv(1, 128);
    CP_COMMIT();
    for (int ti = 0; ti < T; ti++) {
        CP_WAIT1();
        __syncthreads();
        if (ti + 2 < T) {
            int s = ti + 2; while (s >= 3) s -= 3;
            load_kv(s, (ti + 2) * 128);
            CP_COMMIT();
        } else {
            CP_COMMIT();
        }
        int cs = ti; while (cs >= 3) cs -= 3;
        const __half* Ks = smh + cs * ASTG;
        const __half* Vs = Ks + 128 * KPH;
        const int k0 = ti * 128;

        // ---- scores S[m16][n128] ----
        float sf[16][4];
#pragma unroll
        for (int nt = 0; nt < 16; nt++)
#pragma unroll
            for (int r = 0; r < 4; r++) sf[nt][r] = 0.f;
#pragma unroll
        for (int kt = 0; kt < 8; kt++) {
#pragma unroll
            for (int np = 0; np < 8; np++) {
                uint32_t b00, b10, b01, b11;
                const __half* p = Ks + (np * 16 + l15) * KPH + kt * 16 + l16 * 8;
                ldmx4(b00, b10, b01, b11, p);
                mma_f16(sf[2*np    ], qf[kt][0], qf[kt][1], qf[kt][2], qf[kt][3], b00, b01);
                mma_f16(sf[2*np + 1], qf[kt][0], qf[kt][1], qf[kt][2], qf[kt][3], b10, b11);
            }
        }
        bool edge = (k0 + 128 > S_LEN);
#pragma unroll
        for (int nt = 0; nt < 16; nt++) {
#pragma unroll
            for (int r = 0; r < 4; r++) sf[nt][r] *= scale;
            if (edge) {
                int col = k0 + nt * 8 + 2 * t;
                if (col     >= S_LEN) { sf[nt][0] = -1e30f; sf[nt][2] = -1e30f; }
                if (col + 1 >= S_LEN) { sf[nt][1] = -1e30f; sf[nt][3] = -1e30f; }
            }
        }
        // ---- online softmax ----
        float mx0 = -1e30f, mx1 = -1e30f;
#pragma unroll
        for (int nt = 0; nt < 16; nt++) {
            mx0 = fmaxf(mx0, fmaxf(sf[nt][0], sf[nt][1]));
            mx1 = fmaxf(mx1, fmaxf(sf[nt][2], sf[nt][3]));
        }
        mx0 = fmaxf(mx0, __shfl_xor_sync(0xffffffffu, mx0, 1));
        mx0 = fmaxf(mx0, __shfl_xor_sync(0xffffffffu, mx0, 2));
        mx1 = fmaxf(mx1, __shfl_xor_sync(0xffffffffu, mx1, 1));
        mx1 = fmaxf(mx1, __shfl_xor_sync(0xffffffffu, mx1, 2));
        float mn0 = fmaxf(m0, mx0), mn1 = fmaxf(m1, mx1);
        float c0 = __expf(m0 - mn0), c1 = __expf(m1 - mn1);
        float s0 = 0.f, s1 = 0.f;
#pragma unroll
        for (int nt = 0; nt < 16; nt++) {
            sf[nt][0] = __expf(sf[nt][0] - mn0);
            sf[nt][1] = __expf(sf[nt][1] - mn0);
            sf[nt][2] = __expf(sf[nt][2] - mn1);
            sf[nt][3] = __expf(sf[nt][3] - mn1);
            s0 += sf[nt][0] + sf[nt][1];
            s1 += sf[nt][2] + sf[nt][3];
        }
        s0 += __shfl_xor_sync(0xffffffffu, s0, 1);
        s0 += __shfl_xor_sync(0xffffffffu, s0, 2);
        s1 += __shfl_xor_sync(0xffffffffu, s1, 1);
        s1 += __shfl_xor_sync(0xffffffffu, s1, 2);
        l0 = l0 * c0 + s0;  l1 = l1 * c1 + s1;
        m0 = mn0;  m1 = mn1;
#pragma unroll
        for (int nt = 0; nt < 16; nt++) {
            o_acc[nt][0] *= c0; o_acc[nt][1] *= c0;
            o_acc[nt][2] *= c1; o_acc[nt][3] *= c1;
        }
        // ---- O += P @ V ----
        const int vr = lane & 7, vq = lane >> 3;
#pragma unroll
        for (int kt = 0; kt < 8; kt++) {
            uint32_t a0 = pack_h2(sf[2*kt  ][0], sf[2*kt  ][1]);
            uint32_t a1 = pack_h2(sf[2*kt  ][2], sf[2*kt  ][3]);
            uint32_t a2 = pack_h2(sf[2*kt+1][0], sf[2*kt+1][1]);
            uint32_t a3 = pack_h2(sf[2*kt+1][2], sf[2*kt+1][3]);
#pragma unroll
            for (int nb = 0; nb < 8; nb++) {
                const __half* vp = Vs + (kt * 16 + (vq & 1) * 8 + vr) * KPH
                                      + nb * 16 + (vq >> 1) * 8;
                uint32_t v0, v1, v2, v3;
                ldmx4t(v0, v1, v2, v3, vp);
                mma_f16(o_acc[2*nb    ], a0, a1, a2, a3, v0, v1);
                mma_f16(o_acc[2*nb + 1], a0, a1, a2, a3, v2, v3);
            }
        }
    }

    float inv0 = 1.f / l0, inv1 = 1.f / l1;
    int s0r = q0 + warp * 16 + g;
    int s1r = s0r + 8;
#pragma unroll
    for (int nt = 0; nt < 16; nt++) {
        int col = nt * 8 + 2 * t;
        if (s0r < S_LEN)
            *(float2*)(XL + ((size_t)s0r * NH + head) * HD + col) =
                make_float2(o_acc[nt][0] * inv0, o_acc[nt][1] * inv0);
        if (s1r < S_LEN)
            *(float2*)(XL + ((size_t)s1r * NH + head) * HD + col) =
                make_float2(o_acc[nt][2] * inv1, o_acc[nt][3] * inv1);
    }
}

// ---------------- launch ----------------
extern "C" void kernel_launch(void* const* d_in, const int* in_sizes, int n_in,
                              void* d_out, int out_size) {
    const float* x    = (const float*)d_in[0];
    const float* freqs= (const float*)d_in[1];
    const float* gkm  = (const float*)d_in[2];
    const float* gkv  = (const float*)d_in[3];
    const float* Wq   = (const float*)d_in[4];
    const float* bq   = (const float*)d_in[5];
    const float* Wk   = (const float*)d_in[6];
    const float* bk   = (const float*)d_in[7];
    const float* Wv   = (const float*)d_in[8];
    const float* bv   = (const float*)d_in[9];
    const float* Wo   = (const float*)d_in[10];
    const float* bo   = (const float*)d_in[11];
    const float* gq   = (const float*)d_in[12];
    const float* gk   = (const float*)d_in[13];
    const float* Wlin = (const float*)d_in[14];
    const float* blin = (const float*)d_in[15];
    float* out = (float*)d_out;

    float *Qp, *Kp, *XLp, *Zp, *WTp;
    __half *xh, *Wqh, *Wkh, *Wvh, *Woh, *Vh, *RQh, *RKh, *XLh, *G2h;
    cudaGetSymbolAddress((void**)&Qp,  g_Q);
    cudaGetSymbolAddress((void**)&Kp,  g_K);
    cudaGetSymbolAddress((void**)&XLp, g_XL);
    cudaGetSymbolAddress((void**)&Zp,  g_Z);
    cudaGetSymbolAddress((void**)&WTp, g_WT);
    cudaGetSymbolAddress((void**)&xh,  g_xh);
    cudaGetSymbolAddress((void**)&Wqh, g_Wqh);
    cudaGetSymbolAddress((void**)&Wkh, g_Wkh);
    cudaGetSymbolAddress((void**)&Wvh, g_Wvh);
    cudaGetSymbolAddress((void**)&Woh, g_Woh);
    cudaGetSymbolAddress((void**)&Vh,  g_Vh);
    cudaGetSymbolAddress((void**)&RQh, g_RQh);
    cudaGetSymbolAddress((void**)&RKh, g_RKh);
    cudaGetSymbolAddress((void**)&XLh, g_XLh);
    cudaGetSymbolAddress((void**)&G2h, g_G2h);

    cudaFuncSetAttribute(gemm_async_kernel<false>, cudaFuncAttributeMaxDynamicSharedMemorySize, GEMM_SMEM);
    cudaFuncSetAttribute(gemm_async_kernel<true>,  cudaFuncAttributeMaxDynamicSharedMemorySize, GEMM_SMEM);
    cudaFuncSetAttribute(attn_h_kernel, cudaFuncAttributeMaxDynamicSharedMemorySize, ATT_SMEM);
    cudaFuncSetAttribute(xg_mma_kernel, cudaFuncAttributeMaxDynamicSharedMemorySize, XG_SMEM);

    f2h_all_kernel<<<1024, 256>>>(x, Wq, Wk, Wv, Wo, xh, Wqh, Wkh, Wvh, Woh);
    dim3 gemm_grid(DIM / 128, (S_LEN + 127) / 128);
    gemm_async_kernel<false><<<gemm_grid, 256, GEMM_SMEM>>>(xh, Wqh, bq, Qp, S_LEN, DIM, DIM);
    gemm_async_kernel<false><<<gemm_grid, 256, GEMM_SMEM>>>(xh, Wkh, bk, Kp, S_LEN, DIM, DIM);
    gemm_async_kernel<true ><<<gemm_grid, 256, GEMM_SMEM>>>(xh, Wvh, bv, Vh, S_LEN, DIM, DIM);
    qkpost_kernel<true ><<<S_LEN, 384>>>(Qp, gq, gkm, freqs, RQh, Zp);
    qkpost_kernel<false><<<S_LEN, 384>>>(Kp, gk, nullptr, freqs, RKh, nullptr);
    transpose128_kernel<<<HD, HD>>>(Wlin, WTp);
    g2_kernel<<<NH * HD, HD>>>(gkv, WTp, G2h);
    {
        dim3 grid((S_LEN + 127) / 128, NH);
        attn_h_kernel<<<grid, 256, ATT_SMEM>>>(RQh, RKh, Vh, XLp);
    }
    {
        dim3 grid((S_LEN + 127) / 128, NH);
        xg_mma_kernel<<<grid, 256, XG_SMEM>>>(RQh, G2h, Zp, blin, XLp, XLh);
    }
    gemm_async_kernel<false><<<gemm_grid, 256, GEMM_SMEM>>>(XLh, Woh, bo, out, S_LEN, DIM, DIM);
}

// round 9
// speedup vs baseline: 1.0168x; 1.0168x over previous
#include <cuda_runtime.h>
#include <cuda_fp16.h>
#include <math.h>
#include <stdint.h>

#define S_LEN 4680
#define DIM 1536
#define NH 12
#define HD 128

// ---------------- static scratch ----------------
__device__ float  g_Q  [S_LEN*DIM];
__device__ float  g_K  [S_LEN*DIM];
__device__ float  g_XL [S_LEN*DIM];
__device__ float  g_Z  [S_LEN*NH];
__device__ float  g_WT [HD*HD];
__device__ __half g_xh [S_LEN*DIM];
__device__ __half g_Wqh[DIM*DIM];
__device__ __half g_Wkh[DIM*DIM];
__device__ __half g_Wvh[DIM*DIM];
__device__ __half g_Woh[DIM*DIM];
__device__ __half g_Vh [S_LEN*DIM];
__device__ __half g_RQh[S_LEN*DIM];
__device__ __half g_RKh[S_LEN*DIM];
__device__ __half g_XLh[S_LEN*DIM];
__device__ __half g_G2h[NH*HD*HD];   // [n][j][d]

// ---------------- helpers ----------------
__device__ __forceinline__ uint32_t pack_h2(float lo, float hi) {
    __half2 h = __floats2half2_rn(lo, hi);
    return *reinterpret_cast<uint32_t*>(&h);
}
__device__ __forceinline__ void mma_f16(float c[4],
                                        uint32_t a0, uint32_t a1, uint32_t a2, uint32_t a3,
                                        uint32_t b0, uint32_t b1) {
    asm("mma.sync.aligned.m16n8k16.row.col.f32.f16.f16.f32 "
        "{%0,%1,%2,%3},{%4,%5,%6,%7},{%8,%9},{%0,%1,%2,%3};"
        : "+f"(c[0]), "+f"(c[1]), "+f"(c[2]), "+f"(c[3])
        : "r"(a0), "r"(a1), "r"(a2), "r"(a3), "r"(b0), "r"(b1));
}
__device__ __forceinline__ void ldmx4t(uint32_t &r0, uint32_t &r1, uint32_t &r2, uint32_t &r3,
                                       const __half* p) {
    uint32_t addr = (uint32_t)__cvta_generic_to_shared(p);
    asm volatile("ldmatrix.sync.aligned.m8n8.x4.trans.shared.b16 {%0,%1,%2,%3},[%4];"
                 : "=r"(r0), "=r"(r1), "=r"(r2), "=r"(r3) : "r"(addr));
}
__device__ __forceinline__ void cp16(__half* dst, const __half* src, int src_bytes) {
    uint32_t d = (uint32_t)__cvta_generic_to_shared(dst);
    asm volatile("cp.async.cg.shared.global [%0], [%1], 16, %2;"
                 :: "r"(d), "l"(src), "r"(src_bytes));
}
#define CP_COMMIT() asm volatile("cp.async.commit_group;")
#define CP_WAIT0()  asm volatile("cp.async.wait_group 0;")

// ---------------- batched fp32 -> fp16 convert ----------------
__global__ void f2h_all_kernel(const float* __restrict__ x,
                               const float* __restrict__ w0, const float* __restrict__ w1,
                               const float* __restrict__ w2, const float* __restrict__ w3,
                               __half* __restrict__ xh,
                               __half* __restrict__ h0, __half* __restrict__ h1,
                               __half* __restrict__ h2, __half* __restrict__ h3) {
    const int NX = S_LEN * DIM / 4, NW = DIM * DIM / 4;
    const int total = NX + 4 * NW;
    for (int i = blockIdx.x * blockDim.x + threadIdx.x; i < total; i += gridDim.x * blockDim.x) {
        const float* src; __half* dst; int j = i;
        if (j < NX) { src = x; dst = xh; }
        else {
            j -= NX;
            int seg = j / NW; j -= seg * NW;
            src = (seg == 0) ? w0 : (seg == 1) ? w1 : (seg == 2) ? w2 : w3;
            dst = (seg == 0) ? h0 : (seg == 1) ? h1 : (seg == 2) ? h2 : h3;
        }
        float4 v = ((const float4*)src)[j];
        ((uint2*)dst)[j] = make_uint2(pack_h2(v.x, v.y), pack_h2(v.z, v.w));
    }
}

// ---------------- cp.async FP16 GEMM: 64x64 warp tiles ----------------
// Block 128x128, 128 threads / 4 warps (2m x 2n), K-chunk 64, 2-stage.
#define GKP 72
#define GSTG (2 * 128 * GKP)                  // halves per stage (A+B)
#define GEMM_SMEM (2 * GSTG * 2)              // bytes (73.7KB)
template<bool HALF_OUT>
__global__ __launch_bounds__(128, 2) void gemm_async_kernel(
    const __half* __restrict__ A, const __half* __restrict__ W,
    const float* __restrict__ bias, void* __restrict__ Cout,
    int M, int N, int K) {
    extern __shared__ __half gsm[];
    const int tid = threadIdx.x;
    const int warp = tid >> 5, lane = tid & 31;
    const int g = lane >> 2, t = lane & 3;
    const int wm = warp >> 1, wn = warp & 1;
    const int bm = blockIdx.y * 128, bn = blockIdx.x * 128;

    float acc[4][8][4];
#pragma unroll
    for (int i = 0; i < 4; i++)
#pragma unroll
        for (int j = 0; j < 8; j++)
#pragma unroll
            for (int r = 0; r < 4; r++) acc[i][j][r] = 0.f;

    auto load_stage = [&](int s, int k0) {
        __half* As = gsm + s * GSTG;
        __half* Bs = As + 128 * GKP;
#pragma unroll
        for (int it = 0; it < 16; it++) {
            int u = it * 128 + tid;            // 0..2047
            int isB = u >> 10;
            int r = (u >> 3) & 127;
            int c8 = (u & 7) * 8;
            if (!isB) {
                int gm = bm + r;
                const __half* src = A + (size_t)(gm < M ? gm : 0) * K + k0 + c8;
                cp16(As + r * GKP + c8, src, gm < M ? 16 : 0);
            } else {
                const __half* src = W + (size_t)(bn + r) * K + k0 + c8;
                cp16(Bs + r * GKP + c8, src, 16);
            }
        }
    };

    const int nT = K / 64;
    load_stage(0, 0);
    CP_COMMIT();
    for (int i = 0; i < nT; i++) {
        CP_WAIT0();
        __syncthreads();
        if (i + 1 < nT) { load_stage((i + 1) & 1, (i + 1) * 64); CP_COMMIT(); }
        const __half* As = gsm + (i & 1) * GSTG;
        const __half* Bs = As + 128 * GKP;
#pragma unroll
        for (int ks = 0; ks < 4; ks++) {
            int kk = ks * 16;
            uint32_t af[4][4], bf[8][2];
#pragma unroll
            for (int mt = 0; mt < 4; mt++) {
                const __half* p = As + (wm * 64 + mt * 16) * GKP + kk + 2 * t;
                af[mt][0] = *(const uint32_t*)(p + (g    ) * GKP);
                af[mt][1] = *(const uint32_t*)(p + (g + 8) * GKP);
                af[mt][2] = *(const uint32_t*)(p + (g    ) * GKP + 8);
                af[mt][3] = *(const uint32_t*)(p + (g + 8) * GKP + 8);
            }
#pragma unroll
            for (int nt = 0; nt < 8; nt++) {
                const __half* p = Bs + (wn * 64 + nt * 8 + g) * GKP + kk + 2 * t;
                bf[nt][0] = *(const uint32_t*)(p);
                bf[nt][1] = *(const uint32_t*)(p + 8);
            }
#pragma unroll
            for (int mt = 0; mt < 4; mt++)
#pragma unroll
                for (int nt = 0; nt < 8; nt++)
                    mma_f16(acc[mt][nt], af[mt][0], af[mt][1], af[mt][2], af[mt][3],
                            bf[nt][0], bf[nt][1]);
        }
        __syncthreads();
    }
#pragma unroll
    for (int mt = 0; mt < 4; mt++) {
#pragma unroll
        for (int nt = 0; nt < 8; nt++) {
            int col = bn + wn * 64 + nt * 8 + 2 * t;
            float2 b2 = *(const float2*)(bias + col);
            int r0 = bm + wm * 64 + mt * 16 + g;
            int r1 = r0 + 8;
            if (HALF_OUT) {
                __half* Ch = (__half*)Cout;
                if (r0 < M)
                    *(uint32_t*)(Ch + (size_t)r0 * N + col) =
                        pack_h2(acc[mt][nt][0] + b2.x, acc[mt][nt][1] + b2.y);
                if (r1 < M)
                    *(uint32_t*)(Ch + (size_t)r1 * N + col) =
                        pack_h2(acc[mt][nt][2] + b2.x, acc[mt][nt][3] + b2.y);
            } else {
                float* C = (float*)Cout;
                if (r0 < M)
                    *(float2*)(C + (size_t)r0 * N + col) =
                        make_float2(acc[mt][nt][0] + b2.x, acc[mt][nt][1] + b2.y);
                if (r1 < M)
                    *(float2*)(C + (size_t)r1 * N + col) =
                        make_float2(acc[mt][nt][2] + b2.x, acc[mt][nt][3] + b2.y);
            }
        }
    }
}

// ---------------- fused rmsnorm (+z) + rope -> fp16 ----------------
template<bool WITH_Z>
__global__ __launch_bounds__(384) void qkpost_kernel(
    const float* __restrict__ X, const float* __restrict__ gw,
    const float* __restrict__ gkm, const float* __restrict__ freqs,
    __half* __restrict__ Yh, float* __restrict__ Z) {
    __shared__ float vals[DIM];
    __shared__ float red[12];
    __shared__ float s_scale;
    const int s = blockIdx.x;
    const int tid = threadIdx.x;
    const int lane = tid & 31, wid = tid >> 5;
    const float* x = X + (size_t)s * DIM;

    float ss = 0.f;
#pragma unroll
    for (int k = 0; k < 4; k++) {
        int i = tid + k * 384;
        float v = x[i];
        vals[i] = v;
        ss += v * v;
    }
#pragma unroll
    for (int o = 16; o > 0; o >>= 1) ss += __shfl_xor_sync(0xffffffffu, ss, o);
    if (lane == 0) red[wid] = ss;
    __syncthreads();
    if (wid == 0) {
        float v = (lane < 12) ? red[lane] : 0.f;
#pragma unroll
        for (int o = 8; o > 0; o >>= 1) v += __shfl_xor_sync(0xffffffffu, v, o);
        if (lane == 0) s_scale = rsqrtf(v / (float)DIM + 1e-6f);
    }
    __syncthreads();
    const float sc = s_scale;
#pragma unroll
    for (int k = 0; k < 4; k++) {
        int i = tid + k * 384;
        vals[i] = vals[i] * sc * gw[i];
    }
    __syncthreads();
    if (WITH_Z) {
        const float* vh = vals + wid * HD;
        float sum = 0.f;
#pragma unroll
        for (int k = 0; k < 4; k++) {
            int d = lane + k * 32;
            sum += fmaxf(vh[d], 0.f) * gkm[wid * HD + d];
        }
#pragma unroll
        for (int o = 16; o > 0; o >>= 1) sum += __shfl_xor_sync(0xffffffffu, sum, o);
        if (lane == 0) Z[s * NH + wid] = 1.f / (sum + 1e-6f);
    }
    const int w = s % 52, h = (s / 52) % 30, f = s / (52 * 30);
#pragma unroll
    for (int k = 0; k < 2; k++) {
        int p = tid + k * 384;
        int i = p & 63;
        int pos = (i < 22) ? f : (i < 43) ? h : w;
        float cr = freqs[(pos * 64 + i) * 2 + 0];
        float ci = freqs[(pos * 64 + i) * 2 + 1];
        float xr = vals[2 * p], xi = vals[2 * p + 1];
        *(uint32_t*)(Yh + (size_t)s * DIM + 2 * p) =
            pack_h2(xr * cr - xi * ci, xr * ci + xi * cr);
    }
}

// ---------------- Wlin transpose ----------------
__global__ void transpose128_kernel(const float* __restrict__ in, float* __restrict__ out) {
    int j = blockIdx.x, m = threadIdx.x;
    out[m * HD + j] = in[j * HD + m];
}

// ---------------- G2h[n][j][d] ----------------
__global__ void g2_kernel(const float* __restrict__ gkv, const float* __restrict__ WT,
                          __half* __restrict__ G2h) {
    int nd = blockIdx.x;
    int n = nd >> 7, d = nd & 127;
    __shared__ float kv[HD];
    kv[threadIdx.x] = gkv[(size_t)nd * HD + threadIdx.x];
    __syncthreads();
    int j = threadIdx.x;
    float sum = 0.f;
#pragma unroll 8
    for (int m = 0; m < HD; m++) sum += kv[m] * WT[m * HD + j];
    G2h[((size_t)n * HD + j) * HD + d] = __float2half(sum);
}

// ---------------- xg via tensor cores ----------------
#define KPH 136
#define XG_SMEM (2 * 128 * KPH * 2)
__global__ __launch_bounds__(256) void xg_mma_kernel(
    const __half* __restrict__ RQh, const __half* __restrict__ G2h,
    const float* __restrict__ Z, const float* __restrict__ blin,
    const float* __restrict__ XL, __half* __restrict__ XLh) {
    extern __shared__ __half xsm[];
    __half* RQs = xsm;
    __half* G2s = xsm + 128 * KPH;
    const int tid = threadIdx.x;
    const int warp = tid >> 5, lane = tid & 31;
    const int g = lane >> 2, t = lane & 3;
    const int head = blockIdx.y;
    const int q0 = blockIdx.x * 128;

#pragma unroll
    for (int it = 0; it < 8; it++) {
        int f = it * 256 + tid;
        int row = f >> 4, c8 = (f & 15) * 8;
        int s = q0 + row;
        uint4 v = make_uint4(0, 0, 0, 0);
        if (s < S_LEN) v = *(const uint4*)(RQh + ((size_t)s * NH + head) * HD + c8);
        *(uint4*)&RQs[row * KPH + c8] = v;
        uint4 gv = *(const uint4*)(G2h + ((size_t)head * HD + row) * HD + c8);
        *(uint4*)&G2s[row * KPH + c8] = gv;
    }
    __syncthreads();

    uint32_t qf[8][4];
    {
        const __half* p = RQs + (warp * 16) * KPH + 2 * t;
#pragma unroll
        for (int kt = 0; kt < 8; kt++) {
            int kk = kt * 16;
            qf[kt][0] = *(const uint32_t*)(p + (g    ) * KPH + kk);
            qf[kt][1] = *(const uint32_t*)(p + (g + 8) * KPH + kk);
            qf[kt][2] = *(const uint32_t*)(p + (g    ) * KPH + kk + 8);
            qf[kt][3] = *(const uint32_t*)(p + (g + 8) * KPH + kk + 8);
        }
    }
    float acc[16][4];
#pragma unroll
    for (int nt = 0; nt < 16; nt++)
#pragma unroll
        for (int r = 0; r < 4; r++) acc[nt][r] = 0.f;
#pragma unroll
    for (int kt = 0; kt < 8; kt++) {
        int kk = kt * 16 + 2 * t;
#pragma unroll
        for (int nt = 0; nt < 16; nt++) {
            const __half* p = G2s + (nt * 8 + g) * KPH + kk;
            uint32_t b0 = *(const uint32_t*)(p);
            uint32_t b1 = *(const uint32_t*)(p + 8);
            mma_f16(acc[nt], qf[kt][0], qf[kt][1], qf[kt][2], qf[kt][3], b0, b1);
        }
    }
    int s0r = q0 + warp * 16 + g;
    int s1r = s0r + 8;
    float z0 = (s0r < S_LEN) ? Z[s0r * NH + head] : 0.f;
    float z1 = (s1r < S_LEN) ? Z[s1r * NH + head] : 0.f;
#pragma unroll
    for (int nt = 0; nt < 16; nt++) {
        int col = nt * 8 + 2 * t;
        float2 bl = *(const float2*)(blin + col);
        if (s0r < S_LEN) {
            const float* xl = XL + ((size_t)s0r * NH + head) * HD + col;
            *(uint32_t*)(XLh + ((size_t)s0r * NH + head) * HD + col) =
                pack_h2(acc[nt][0] * z0 + bl.x + xl[0], acc[nt][1] * z0 + bl.y + xl[1]);
        }
        if (s1r < S_LEN) {
            const float* xl = XL + ((size_t)s1r * NH + head) * HD + col;
            *(uint32_t*)(XLh + ((size_t)s1r * NH + head) * HD + col) =
                pack_h2(acc[nt][2] * z1 + bl.x + xl[0], acc[nt][3] * z1 + bl.y + xl[1]);
        }
    }
}

// ---------------- FP16 flash attention, Bc=128, cp.async 2-stage ----------------
#define ASTG (2 * 128 * KPH)
#define ATT_SMEM (2 * ASTG * 2)
__global__ __launch_bounds__(256, 1) void attn_h_kernel(
    const __half* __restrict__ RQh, const __half* __restrict__ RKh,
    const __half* __restrict__ Vh, float* __restrict__ XL) {
    extern __shared__ __half smh[];
    const int tid = threadIdx.x;
    const int warp = tid >> 5, lane = tid & 31;
    const int g = lane >> 2, t = lane & 3;
    const int head = blockIdx.y;
    const int q0 = blockIdx.x * 128;

    {
        __half* Qs = smh;
#pragma unroll
        for (int it = 0; it < 8; it++) {
            int f = it * 256 + tid;
            int row = f >> 4, c8 = (f & 15) * 8;
            int s = q0 + row;
            uint4 v = make_uint4(0, 0, 0, 0);
            if (s < S_LEN) v = *(const uint4*)(RQh + ((size_t)s * NH + head) * HD + c8);
            *(uint4*)&Qs[row * KPH + c8] = v;
        }
    }
    __syncthreads();
    uint32_t qf[8][4];
    {
        const __half* p = smh + (warp * 16) * KPH + 2 * t;
#pragma unroll
        for (int kt = 0; kt < 8; kt++) {
            int kk = kt * 16;
            qf[kt][0] = *(const uint32_t*)(p + (g    ) * KPH + kk);
            qf[kt][1] = *(const uint32_t*)(p + (g + 8) * KPH + kk);
            qf[kt][2] = *(const uint32_t*)(p + (g    ) * KPH + kk + 8);
            qf[kt][3] = *(const uint32_t*)(p + (g + 8) * KPH + kk + 8);
        }
    }
    __syncthreads();

    auto load_kv = [&](int st, int k0) {
        __half* Ks = smh + st * ASTG;
        __half* Vs = Ks + 128 * KPH;
#pragma unroll
        for (int it = 0; it < 8; it++) {
            int f = it * 256 + tid;
            int row = f >> 4, c8 = (f & 15) * 8;
            int s = k0 + row;
            int sb = (s < S_LEN) ? 16 : 0;
            size_t off = ((size_t)(s < S_LEN ? s : S_LEN - 1) * NH + head) * HD + c8;
            cp16(Ks + row * KPH + c8, RKh + off, sb);
            cp16(Vs + row * KPH + c8, Vh + off, sb);
        }
    };

    float o_acc[16][4];
#pragma unroll
    for (int nt = 0; nt < 16; nt++)
#pragma unroll
        for (int r = 0; r < 4; r++) o_acc[nt][r] = 0.f;
    float m0 = -1e30f, m1 = -1e30f, l0 = 0.f, l1 = 0.f;
    const float scale = 0.08838834764831845f;
    const int T = (S_LEN + 127) / 128;

    load_kv(0, 0);
    CP_COMMIT();
    for (int ti = 0; ti < T; ti++) {
        CP_WAIT0();
        __syncthreads();
        if (ti + 1 < T) { load_kv((ti + 1) & 1, (ti + 1) * 128); CP_COMMIT(); }
        const __half* Ks = smh + (ti & 1) * ASTG;
        const __half* Vs = Ks + 128 * KPH;
        const int k0 = ti * 128;

        float sf[16][4];
#pragma unroll
        for (int nt = 0; nt < 16; nt++)
#pragma unroll
            for (int r = 0; r < 4; r++) sf[nt][r] = 0.f;
#pragma unroll
        for (int kt = 0; kt < 8; kt++) {
            int kk = kt * 16 + 2 * t;
#pragma unroll
            for (int nt = 0; nt < 16; nt++) {
                const __half* p = Ks + (nt * 8 + g) * KPH + kk;
                uint32_t b0 = *(const uint32_t*)(p);
                uint32_t b1 = *(const uint32_t*)(p + 8);
                mma_f16(sf[nt], qf[kt][0], qf[kt][1], qf[kt][2], qf[kt][3], b0, b1);
            }
        }
        bool edge = (k0 + 128 > S_LEN);
#pragma unroll
        for (int nt = 0; nt < 16; nt++) {
#pragma unroll
            for (int r = 0; r < 4; r++) sf[nt][r] *= scale;
            if (edge) {
                int col = k0 + nt * 8 + 2 * t;
                if (col     >= S_LEN) { sf[nt][0] = -1e30f; sf[nt][2] = -1e30f; }
                if (col + 1 >= S_LEN) { sf[nt][1] = -1e30f; sf[nt][3] = -1e30f; }
            }
        }
        float mx0 = -1e30f, mx1 = -1e30f;
#pragma unroll
        for (int nt = 0; nt < 16; nt++) {
            mx0 = fmaxf(mx0, fmaxf(sf[nt][0], sf[nt][1]));
            mx1 = fmaxf(mx1, fmaxf(sf[nt][2], sf[nt][3]));
        }
        mx0 = fmaxf(mx0, __shfl_xor_sync(0xffffffffu, mx0, 1));
        mx0 = fmaxf(mx0, __shfl_xor_sync(0xffffffffu, mx0, 2));
        mx1 = fmaxf(mx1, __shfl_xor_sync(0xffffffffu, mx1, 1));
        mx1 = fmaxf(mx1, __shfl_xor_sync(0xffffffffu, mx1, 2));
        float mn0 = fmaxf(m0, mx0), mn1 = fmaxf(m1, mx1);
        float c0 = __expf(m0 - mn0), c1 = __expf(m1 - mn1);
        float s0 = 0.f, s1 = 0.f;
#pragma unroll
        for (int nt = 0; nt < 16; nt++) {
            sf[nt][0] = __expf(sf[nt][0] - mn0);
            sf[nt][1] = __expf(sf[nt][1] - mn0);
            sf[nt][2] = __expf(sf[nt][2] - mn1);
            sf[nt][3] = __expf(sf[nt][3] - mn1);
            s0 += sf[nt][0] + sf[nt][1];
            s1 += sf[nt][2] + sf[nt][3];
        }
        s0 += __shfl_xor_sync(0xffffffffu, s0, 1);
        s0 += __shfl_xor_sync(0xffffffffu, s0, 2);
        s1 += __shfl_xor_sync(0xffffffffu, s1, 1);
        s1 += __shfl_xor_sync(0xffffffffu, s1, 2);
        l0 = l0 * c0 + s0;  l1 = l1 * c1 + s1;
        m0 = mn0;  m1 = mn1;
#pragma unroll
        for (int nt = 0; nt < 16; nt++) {
            o_acc[nt][0] *= c0; o_acc[nt][1] *= c0;
            o_acc[nt][2] *= c1; o_acc[nt][3] *= c1;
        }
        const int vr = lane & 7, vq = lane >> 3;
#pragma unroll
        for (int kt = 0; kt < 8; kt++) {
            uint32_t a0 = pack_h2(sf[2*kt  ][0], sf[2*kt  ][1]);
            uint32_t a1 = pack_h2(sf[2*kt  ][2], sf[2*kt  ][3]);
            uint32_t a2 = pack_h2(sf[2*kt+1][0], sf[2*kt+1][1]);
            uint32_t a3 = pack_h2(sf[2*kt+1][2], sf[2*kt+1][3]);
#pragma unroll
            for (int nb = 0; nb < 8; nb++) {
                const __half* vp = Vs + (kt * 16 + (vq & 1) * 8 + vr) * KPH
                                      + nb * 16 + (vq >> 1) * 8;
                uint32_t v0, v1, v2, v3;
                ldmx4t(v0, v1, v2, v3, vp);
                mma_f16(o_acc[2*nb    ], a0, a1, a2, a3, v0, v1);
                mma_f16(o_acc[2*nb + 1], a0, a1, a2, a3, v2, v3);
            }
        }
        __syncthreads();
    }

    float inv0 = 1.f / l0, inv1 = 1.f / l1;
    int s0r = q0 + warp * 16 + g;
    int s1r = s0r + 8;
#pragma unroll
    for (int nt = 0; nt < 16; nt++) {
        int col = nt * 8 + 2 * t;
        if (s0r < S_LEN)
            *(float2*)(XL + ((size_t)s0r * NH + head) * HD + col) =
                make_float2(o_acc[nt][0] * inv0, o_acc[nt][1] * inv0);
        if (s1r < S_LEN)
            *(float2*)(XL + ((size_t)s1r * NH + head) * HD + col) =
                make_float2(o_acc[nt][2] * inv1, o_acc[nt][3] * inv1);
    }
}

// ---------------- launch ----------------
extern "C" void kernel_launch(void* const* d_in, const int* in_sizes, int n_in,
                              void* d_out, int out_size) {
    const float* x    = (const float*)d_in[0];
    const float* freqs= (const float*)d_in[1];
    const float* gkm  = (const float*)d_in[2];
    const float* gkv  = (const float*)d_in[3];
    const float* Wq   = (const float*)d_in[4];
    const float* bq   = (const float*)d_in[5];
    const float* Wk   = (const float*)d_in[6];
    const float* bk   = (const float*)d_in[7];
    const float* Wv   = (const float*)d_in[8];
    const float* bv   = (const float*)d_in[9];
    const float* Wo   = (const float*)d_in[10];
    const float* bo   = (const float*)d_in[11];
    const float* gq   = (const float*)d_in[12];
    const float* gk   = (const float*)d_in[13];
    const float* Wlin = (const float*)d_in[14];
    const float* blin = (const float*)d_in[15];
    float* out = (float*)d_out;

    float *Qp, *Kp, *XLp, *Zp, *WTp;
    __half *xh, *Wqh, *Wkh, *Wvh, *Woh, *Vh, *RQh, *RKh, *XLh, *G2h;
    cudaGetSymbolAddress((void**)&Qp,  g_Q);
    cudaGetSymbolAddress((void**)&Kp,  g_K);
    cudaGetSymbolAddress((void**)&XLp, g_XL);
    cudaGetSymbolAddress((void**)&Zp,  g_Z);
    cudaGetSymbolAddress((void**)&WTp, g_WT);
    cudaGetSymbolAddress((void**)&xh,  g_xh);
    cudaGetSymbolAddress((void**)&Wqh, g_Wqh);
    cudaGetSymbolAddress((void**)&Wkh, g_Wkh);
    cudaGetSymbolAddress((void**)&Wvh, g_Wvh);
    cudaGetSymbolAddress((void**)&Woh, g_Woh);
    cudaGetSymbolAddress((void**)&Vh,  g_Vh);
    cudaGetSymbolAddress((void**)&RQh, g_RQh);
    cudaGetSymbolAddress((void**)&RKh, g_RKh);
    cudaGetSymbolAddress((void**)&XLh, g_XLh);
    cudaGetSymbolAddress((void**)&G2h, g_G2h);

    cudaFuncSetAttribute(gemm_async_kernel<false>, cudaFuncAttributeMaxDynamicSharedMemorySize, GEMM_SMEM);
    cudaFuncSetAttribute(gemm_async_kernel<true>,  cudaFuncAttributeMaxDynamicSharedMemorySize, GEMM_SMEM);
    cudaFuncSetAttribute(attn_h_kernel, cudaFuncAttributeMaxDynamicSharedMemorySize, ATT_SMEM);
    cudaFuncSetAttribute(xg_mma_kernel, cudaFuncAttributeMaxDynamicSharedMemorySize, XG_SMEM);

    f2h_all_kernel<<<1024, 256>>>(x, Wq, Wk, Wv, Wo, xh, Wqh, Wkh, Wvh, Woh);
    dim3 gemm_grid(DIM / 128, (S_LEN + 127) / 128);
    gemm_async_kernel<false><<<gemm_grid, 128, GEMM_SMEM>>>(xh, Wqh, bq, Qp, S_LEN, DIM, DIM);
    gemm_async_kernel<false><<<gemm_grid, 128, GEMM_SMEM>>>(xh, Wkh, bk, Kp, S_LEN, DIM, DIM);
    gemm_async_kernel<true ><<<gemm_grid, 128, GEMM_SMEM>>>(xh, Wvh, bv, Vh, S_LEN, DIM, DIM);
    qkpost_kernel<true ><<<S_LEN, 384>>>(Qp, gq, gkm, freqs, RQh, Zp);
    qkpost_kernel<false><<<S_LEN, 384>>>(Kp, gk, nullptr, freqs, RKh, nullptr);
    transpose128_kernel<<<HD, HD>>>(Wlin, WTp);
    g2_kernel<<<NH * HD, HD>>>(gkv, WTp, G2h);
    {
        dim3 grid((S_LEN + 127) / 128, NH);
        attn_h_kernel<<<grid, 256, ATT_SMEM>>>(RQh, RKh, Vh, XLp);
    }
    {
        dim3 grid((S_LEN + 127) / 128, NH);
        xg_mma_kernel<<<grid, 256, XG_SMEM>>>(RQh, G2h, Zp, blin, XLp, XLh);
    }
    gemm_async_kernel<false><<<gemm_grid, 128, GEMM_SMEM>>>(XLh, Woh, bo, out, S_LEN, DIM, DIM);
}

// round 10
// speedup vs baseline: 1.0506x; 1.0332x over previous
#include <cuda_runtime.h>
#include <cuda_fp16.h>
#include <math.h>
#include <stdint.h>

#define S_LEN 4680
#define DIM 1536
#define NH 12
#define HD 128

// ---------------- static scratch ----------------
__device__ float  g_Q  [S_LEN*DIM];
__device__ float  g_K  [S_LEN*DIM];
__device__ float  g_XL [S_LEN*DIM];
__device__ float  g_Z  [S_LEN*NH];
__device__ float  g_WT [HD*HD];
__device__ float  g_bqkv[3*DIM];
__device__ __half g_xh [S_LEN*DIM];
__device__ __half g_Wqkvh[3*DIM*DIM];   // Wq | Wk | Wv
__device__ __half g_Woh[DIM*DIM];
__device__ __half g_Vh [S_LEN*DIM];
__device__ __half g_RQh[S_LEN*DIM];
__device__ __half g_RKh[S_LEN*DIM];
__device__ __half g_XLh[S_LEN*DIM];
__device__ __half g_G2h[NH*HD*HD];   // [n][j][d]

// ---------------- helpers ----------------
__device__ __forceinline__ uint32_t pack_h2(float lo, float hi) {
    __half2 h = __floats2half2_rn(lo, hi);
    return *reinterpret_cast<uint32_t*>(&h);
}
__device__ __forceinline__ void mma_f16(float c[4],
                                        uint32_t a0, uint32_t a1, uint32_t a2, uint32_t a3,
                                        uint32_t b0, uint32_t b1) {
    asm("mma.sync.aligned.m16n8k16.row.col.f32.f16.f16.f32 "
        "{%0,%1,%2,%3},{%4,%5,%6,%7},{%8,%9},{%0,%1,%2,%3};"
        : "+f"(c[0]), "+f"(c[1]), "+f"(c[2]), "+f"(c[3])
        : "r"(a0), "r"(a1), "r"(a2), "r"(a3), "r"(b0), "r"(b1));
}
__device__ __forceinline__ void ldmx4t(uint32_t &r0, uint32_t &r1, uint32_t &r2, uint32_t &r3,
                                       const __half* p) {
    uint32_t addr = (uint32_t)__cvta_generic_to_shared(p);
    asm volatile("ldmatrix.sync.aligned.m8n8.x4.trans.shared.b16 {%0,%1,%2,%3},[%4];"
                 : "=r"(r0), "=r"(r1), "=r"(r2), "=r"(r3) : "r"(addr));
}
__device__ __forceinline__ void cp16(__half* dst, const __half* src, int src_bytes) {
    uint32_t d = (uint32_t)__cvta_generic_to_shared(dst);
    asm volatile("cp.async.cg.shared.global [%0], [%1], 16, %2;"
                 :: "r"(d), "l"(src), "r"(src_bytes));
}
#define CP_COMMIT() asm volatile("cp.async.commit_group;")
#define CP_WAIT0()  asm volatile("cp.async.wait_group 0;")

// ---------------- batched convert: x + 4 weights -> fp16, biases -> concat ----------------
__global__ void f2h_all_kernel(const float* __restrict__ x,
                               const float* __restrict__ w0, const float* __restrict__ w1,
                               const float* __restrict__ w2, const float* __restrict__ w3,
                               const float* __restrict__ bq, const float* __restrict__ bk,
                               const float* __restrict__ bv,
                               __half* __restrict__ xh, __half* __restrict__ wqkv,
                               __half* __restrict__ woh, float* __restrict__ bqkv) {
    const int NX = S_LEN * DIM / 4, NW = DIM * DIM / 4, NB = DIM / 4;
    const int total = NX + 4 * NW + 3 * NB;
    for (int i = blockIdx.x * blockDim.x + threadIdx.x; i < total; i += gridDim.x * blockDim.x) {
        int j = i;
        if (j < NX + 4 * NW) {
            const float* src; __half* dst;
            if (j < NX) { src = x; dst = xh; }
            else {
                j -= NX;
                int seg = j / NW; j -= seg * NW;
                src = (seg == 0) ? w0 : (seg == 1) ? w1 : (seg == 2) ? w2 : w3;
                dst = (seg == 3) ? woh : wqkv + (size_t)seg * DIM * DIM;
            }
            float4 v = ((const float4*)src)[j];
            ((uint2*)dst)[j] = make_uint2(pack_h2(v.x, v.y), pack_h2(v.z, v.w));
        } else {
            j -= NX + 4 * NW;
            int seg = j / NB; j -= seg * NB;
            const float* src = (seg == 0) ? bq : (seg == 1) ? bk : bv;
            ((float4*)bqkv)[seg * NB + j] = ((const float4*)src)[j];
        }
    }
}

// ---------------- GEMM mainloop macro pieces (256 thr, 8 warps, 2-stage) ----------------
#define GKP 72
#define GSTG (2 * 128 * GKP)
#define GEMM_SMEM (2 * GSTG * 2)

// ---------------- fused QKV GEMM: N = 3*DIM, epilogue routes per segment ----------------
__global__ __launch_bounds__(256, 2) void gemm_qkv_kernel(
    const __half* __restrict__ A, const __half* __restrict__ W,
    const float* __restrict__ bqkv,
    float* __restrict__ Qo, float* __restrict__ Ko, __half* __restrict__ Vo) {
    extern __shared__ __half gsm[];
    const int M = S_LEN, K = DIM;
    const int tid = threadIdx.x;
    const int warp = tid >> 5, lane = tid & 31;
    const int g = lane >> 2, t = lane & 3;
    const int wm = warp >> 2, wn = warp & 3;
    const int bm = blockIdx.y * 128, bn = blockIdx.x * 128;

    float acc[4][4][4];
#pragma unroll
    for (int i = 0; i < 4; i++)
#pragma unroll
        for (int j = 0; j < 4; j++)
#pragma unroll
            for (int r = 0; r < 4; r++) acc[i][j][r] = 0.f;

    auto load_stage = [&](int s, int k0) {
        __half* As = gsm + s * GSTG;
        __half* Bs = As + 128 * GKP;
#pragma unroll
        for (int it = 0; it < 4; it++) {
            int f = it * 256 + tid;
            int row = f >> 3, c8 = (f & 7) * 8;
            int gm = bm + row;
            const __half* sa = A + (size_t)(gm < M ? gm : M - 1) * K + k0 + c8;
            cp16(As + row * GKP + c8, sa, gm < M ? 16 : 0);
            const __half* sb = W + (size_t)(bn + row) * K + k0 + c8;
            cp16(Bs + row * GKP + c8, sb, 16);
        }
    };

    const int nT = K / 64;
    load_stage(0, 0);
    CP_COMMIT();
    for (int i = 0; i < nT; i++) {
        CP_WAIT0();
        __syncthreads();
        if (i + 1 < nT) { load_stage((i + 1) & 1, (i + 1) * 64); CP_COMMIT(); }
        const __half* As = gsm + (i & 1) * GSTG;
        const __half* Bs = As + 128 * GKP;
#pragma unroll
        for (int ks = 0; ks < 4; ks++) {
            int kk = ks * 16;
            uint32_t af[4][4], bf[4][2];
#pragma unroll
            for (int mt = 0; mt < 4; mt++) {
                const __half* p = As + (wm * 64 + mt * 16) * GKP + kk + 2 * t;
                af[mt][0] = *(const uint32_t*)(p + (g    ) * GKP);
                af[mt][1] = *(const uint32_t*)(p + (g + 8) * GKP);
                af[mt][2] = *(const uint32_t*)(p + (g    ) * GKP + 8);
                af[mt][3] = *(const uint32_t*)(p + (g + 8) * GKP + 8);
            }
#pragma unroll
            for (int nt = 0; nt < 4; nt++) {
                const __half* p = Bs + (wn * 32 + nt * 8 + g) * GKP + kk + 2 * t;
                bf[nt][0] = *(const uint32_t*)(p);
                bf[nt][1] = *(const uint32_t*)(p + 8);
            }
#pragma unroll
            for (int mt = 0; mt < 4; mt++)
#pragma unroll
                for (int nt = 0; nt < 4; nt++)
                    mma_f16(acc[mt][nt], af[mt][0], af[mt][1], af[mt][2], af[mt][3],
                            bf[nt][0], bf[nt][1]);
        }
        __syncthreads();
    }
    // epilogue: whole CTA lies in one segment (DIM % 128 == 0)
    const int seg = bn / DIM;
    const int colbase = bn - seg * DIM;
    const float* bias = bqkv + seg * DIM;
#pragma unroll
    for (int mt = 0; mt < 4; mt++) {
#pragma unroll
        for (int nt = 0; nt < 4; nt++) {
            int col = colbase + wn * 32 + nt * 8 + 2 * t;
            float2 b2 = *(const float2*)(bias + col);
            int r0 = bm + wm * 64 + mt * 16 + g;
            int r1 = r0 + 8;
            float v00 = acc[mt][nt][0] + b2.x, v01 = acc[mt][nt][1] + b2.y;
            float v10 = acc[mt][nt][2] + b2.x, v11 = acc[mt][nt][3] + b2.y;
            if (seg == 2) {
                if (r0 < M) *(uint32_t*)(Vo + (size_t)r0 * DIM + col) = pack_h2(v00, v01);
                if (r1 < M) *(uint32_t*)(Vo + (size_t)r1 * DIM + col) = pack_h2(v10, v11);
            } else {
                float* C = (seg == 0) ? Qo : Ko;
                if (r0 < M) *(float2*)(C + (size_t)r0 * DIM + col) = make_float2(v00, v01);
                if (r1 < M) *(float2*)(C + (size_t)r1 * DIM + col) = make_float2(v10, v11);
            }
        }
    }
}

// ---------------- standard GEMM (out projection): C = A @ W^T + bias, fp32 out ----------------
__global__ __launch_bounds__(256, 2) void gemm_async_kernel(
    const __half* __restrict__ A, const __half* __restrict__ W,
    const float* __restrict__ bias, float* __restrict__ C,
    int M, int N, int K) {
    extern __shared__ __half gsm[];
    const int tid = threadIdx.x;
    const int warp = tid >> 5, lane = tid & 31;
    const int g = lane >> 2, t = lane & 3;
    const int wm = warp >> 2, wn = warp & 3;
    const int bm = blockIdx.y * 128, bn = blockIdx.x * 128;

    float acc[4][4][4];
#pragma unroll
    for (int i = 0; i < 4; i++)
#pragma unroll
        for (int j = 0; j < 4; j++)
#pragma unroll
            for (int r = 0; r < 4; r++) acc[i][j][r] = 0.f;

    auto load_stage = [&](int s, int k0) {
        __half* As = gsm + s * GSTG;
        __half* Bs = As + 128 * GKP;
#pragma unroll
        for (int it = 0; it < 4; it++) {
            int f = it * 256 + tid;
            int row = f >> 3, c8 = (f & 7) * 8;
            int gm = bm + row;
            const __half* sa = A + (size_t)(gm < M ? gm : M - 1) * K + k0 + c8;
            cp16(As + row * GKP + c8, sa, gm < M ? 16 : 0);
            const __half* sb = W + (size_t)(bn + row) * K + k0 + c8;
            cp16(Bs + row * GKP + c8, sb, 16);
        }
    };

    const int nT = K / 64;
    load_stage(0, 0);
    CP_COMMIT();
    for (int i = 0; i < nT; i++) {
        CP_WAIT0();
        __syncthreads();
        if (i + 1 < nT) { load_stage((i + 1) & 1, (i + 1) * 64); CP_COMMIT(); }
        const __half* As = gsm + (i & 1) * GSTG;
        const __half* Bs = As + 128 * GKP;
#pragma unroll
        for (int ks = 0; ks < 4; ks++) {
            int kk = ks * 16;
            uint32_t af[4][4], bf[4][2];
#pragma unroll
            for (int mt = 0; mt < 4; mt++) {
                const __half* p = As + (wm * 64 + mt * 16) * GKP + kk + 2 * t;
                af[mt][0] = *(const uint32_t*)(p + (g    ) * GKP);
                af[mt][1] = *(const uint32_t*)(p + (g + 8) * GKP);
                af[mt][2] = *(const uint32_t*)(p + (g    ) * GKP + 8);
                af[mt][3] = *(const uint32_t*)(p + (g + 8) * GKP + 8);
            }
#pragma unroll
            for (int nt = 0; nt < 4; nt++) {
                const __half* p = Bs + (wn * 32 + nt * 8 + g) * GKP + kk + 2 * t;
                bf[nt][0] = *(const uint32_t*)(p);
                bf[nt][1] = *(const uint32_t*)(p + 8);
            }
#pragma unroll
            for (int mt = 0; mt < 4; mt++)
#pragma unroll
                for (int nt = 0; nt < 4; nt++)
                    mma_f16(acc[mt][nt], af[mt][0], af[mt][1], af[mt][2], af[mt][3],
                            bf[nt][0], bf[nt][1]);
        }
        __syncthreads();
    }
#pragma unroll
    for (int mt = 0; mt < 4; mt++) {
#pragma unroll
        for (int nt = 0; nt < 4; nt++) {
            int col = bn + wn * 32 + nt * 8 + 2 * t;
            float2 b2 = *(const float2*)(bias + col);
            int r0 = bm + wm * 64 + mt * 16 + g;
            int r1 = r0 + 8;
            if (r0 < M)
                *(float2*)(C + (size_t)r0 * N + col) =
                    make_float2(acc[mt][nt][0] + b2.x, acc[mt][nt][1] + b2.y);
            if (r1 < M)
                *(float2*)(C + (size_t)r1 * N + col) =
                    make_float2(acc[mt][nt][2] + b2.x, acc[mt][nt][3] + b2.y);
        }
    }
}

// ---------------- fused rmsnorm (+z) + rope -> fp16 ----------------
template<bool WITH_Z>
__global__ __launch_bounds__(384) void qkpost_kernel(
    const float* __restrict__ X, const float* __restrict__ gw,
    const float* __restrict__ gkm, const float* __restrict__ freqs,
    __half* __restrict__ Yh, float* __restrict__ Z) {
    __shared__ float vals[DIM];
    __shared__ float red[12];
    __shared__ float s_scale;
    const int s = blockIdx.x;
    const int tid = threadIdx.x;
    const int lane = tid & 31, wid = tid >> 5;
    const float* x = X + (size_t)s * DIM;

    float ss = 0.f;
#pragma unroll
    for (int k = 0; k < 4; k++) {
        int i = tid + k * 384;
        float v = x[i];
        vals[i] = v;
        ss += v * v;
    }
#pragma unroll
    for (int o = 16; o > 0; o >>= 1) ss += __shfl_xor_sync(0xffffffffu, ss, o);
    if (lane == 0) red[wid] = ss;
    __syncthreads();
    if (wid == 0) {
        float v = (lane < 12) ? red[lane] : 0.f;
#pragma unroll
        for (int o = 8; o > 0; o >>= 1) v += __shfl_xor_sync(0xffffffffu, v, o);
        if (lane == 0) s_scale = rsqrtf(v / (float)DIM + 1e-6f);
    }
    __syncthreads();
    const float sc = s_scale;
#pragma unroll
    for (int k = 0; k < 4; k++) {
        int i = tid + k * 384;
        vals[i] = vals[i] * sc * gw[i];
    }
    __syncthreads();
    if (WITH_Z) {
        const float* vh = vals + wid * HD;
        float sum = 0.f;
#pragma unroll
        for (int k = 0; k < 4; k++) {
            int d = lane + k * 32;
            sum += fmaxf(vh[d], 0.f) * gkm[wid * HD + d];
        }
#pragma unroll
        for (int o = 16; o > 0; o >>= 1) sum += __shfl_xor_sync(0xffffffffu, sum, o);
        if (lane == 0) Z[s * NH + wid] = 1.f / (sum + 1e-6f);
    }
    const int w = s % 52, h = (s / 52) % 30, f = s / (52 * 30);
#pragma unroll
    for (int k = 0; k < 2; k++) {
        int p = tid + k * 384;
        int i = p & 63;
        int pos = (i < 22) ? f : (i < 43) ? h : w;
        float cr = freqs[(pos * 64 + i) * 2 + 0];
        float ci = freqs[(pos * 64 + i) * 2 + 1];
        float xr = vals[2 * p], xi = vals[2 * p + 1];
        *(uint32_t*)(Yh + (size_t)s * DIM + 2 * p) =
            pack_h2(xr * cr - xi * ci, xr * ci + xi * cr);
    }
}

// ---------------- Wlin transpose ----------------
__global__ void transpose128_kernel(const float* __restrict__ in, float* __restrict__ out) {
    int j = blockIdx.x, m = threadIdx.x;
    out[m * HD + j] = in[j * HD + m];
}

// ---------------- G2h[n][j][d] ----------------
__global__ void g2_kernel(const float* __restrict__ gkv, const float* __restrict__ WT,
                          __half* __restrict__ G2h) {
    int nd = blockIdx.x;
    int n = nd >> 7, d = nd & 127;
    __shared__ float kv[HD];
    kv[threadIdx.x] = gkv[(size_t)nd * HD + threadIdx.x];
    __syncthreads();
    int j = threadIdx.x;
    float sum = 0.f;
#pragma unroll 8
    for (int m = 0; m < HD; m++) sum += kv[m] * WT[m * HD + j];
    G2h[((size_t)n * HD + j) * HD + d] = __float2half(sum);
}

// ---------------- xg via tensor cores ----------------
#define KPH 136
#define XG_SMEM (2 * 128 * KPH * 2)
__global__ __launch_bounds__(256) void xg_mma_kernel(
    const __half* __restrict__ RQh, const __half* __restrict__ G2h,
    const float* __restrict__ Z, const float* __restrict__ blin,
    const float* __restrict__ XL, __half* __restrict__ XLh) {
    extern __shared__ __half xsm[];
    __half* RQs = xsm;
    __half* G2s = xsm + 128 * KPH;
    const int tid = threadIdx.x;
    const int warp = tid >> 5, lane = tid & 31;
    const int g = lane >> 2, t = lane & 3;
    const int head = blockIdx.y;
    const int q0 = blockIdx.x * 128;

#pragma unroll
    for (int it = 0; it < 8; it++) {
        int f = it * 256 + tid;
        int row = f >> 4, c8 = (f & 15) * 8;
        int s = q0 + row;
        uint4 v = make_uint4(0, 0, 0, 0);
        if (s < S_LEN) v = *(const uint4*)(RQh + ((size_t)s * NH + head) * HD + c8);
        *(uint4*)&RQs[row * KPH + c8] = v;
        uint4 gv = *(const uint4*)(G2h + ((size_t)head * HD + row) * HD + c8);
        *(uint4*)&G2s[row * KPH + c8] = gv;
    }
    __syncthreads();

    uint32_t qf[8][4];
    {
        const __half* p = RQs + (warp * 16) * KPH + 2 * t;
#pragma unroll
        for (int kt = 0; kt < 8; kt++) {
            int kk = kt * 16;
            qf[kt][0] = *(const uint32_t*)(p + (g    ) * KPH + kk);
            qf[kt][1] = *(const uint32_t*)(p + (g + 8) * KPH + kk);
            qf[kt][2] = *(const uint32_t*)(p + (g    ) * KPH + kk + 8);
            qf[kt][3] = *(const uint32_t*)(p + (g + 8) * KPH + kk + 8);
        }
    }
    float acc[16][4];
#pragma unroll
    for (int nt = 0; nt < 16; nt++)
#pragma unroll
        for (int r = 0; r < 4; r++) acc[nt][r] = 0.f;
#pragma unroll
    for (int kt = 0; kt < 8; kt++) {
        int kk = kt * 16 + 2 * t;
#pragma unroll
        for (int nt = 0; nt < 16; nt++) {
            const __half* p = G2s + (nt * 8 + g) * KPH + kk;
            uint32_t b0 = *(const uint32_t*)(p);
            uint32_t b1 = *(const uint32_t*)(p + 8);
            mma_f16(acc[nt], qf[kt][0], qf[kt][1], qf[kt][2], qf[kt][3], b0, b1);
        }
    }
    int s0r = q0 + warp * 16 + g;
    int s1r = s0r + 8;
    float z0 = (s0r < S_LEN) ? Z[s0r * NH + head] : 0.f;
    float z1 = (s1r < S_LEN) ? Z[s1r * NH + head] : 0.f;
#pragma unroll
    for (int nt = 0; nt < 16; nt++) {
        int col = nt * 8 + 2 * t;
        float2 bl = *(const float2*)(blin + col);
        if (s0r < S_LEN) {
            const float* xl = XL + ((size_t)s0r * NH + head) * HD + col;
            *(uint32_t*)(XLh + ((size_t)s0r * NH + head) * HD + col) =
                pack_h2(acc[nt][0] * z0 + bl.x + xl[0], acc[nt][1] * z0 + bl.y + xl[1]);
        }
        if (s1r < S_LEN) {
            const float* xl = XL + ((size_t)s1r * NH + head) * HD + col;
            *(uint32_t*)(XLh + ((size_t)s1r * NH + head) * HD + col) =
                pack_h2(acc[nt][2] * z1 + bl.x + xl[0], acc[nt][3] * z1 + bl.y + xl[1]);
        }
    }
}

// ---------------- FP16 flash attention, Bc=128, cp.async 2-stage ----------------
#define ASTG (2 * 128 * KPH)
#define ATT_SMEM (2 * ASTG * 2)
__global__ __launch_bounds__(256, 1) void attn_h_kernel(
    const __half* __restrict__ RQh, const __half* __restrict__ RKh,
    const __half* __restrict__ Vh, float* __restrict__ XL) {
    extern __shared__ __half smh[];
    const int tid = threadIdx.x;
    const int warp = tid >> 5, lane = tid & 31;
    const int g = lane >> 2, t = lane & 3;
    const int head = blockIdx.y;
    const int q0 = blockIdx.x * 128;

    {
        __half* Qs = smh;
#pragma unroll
        for (int it = 0; it < 8; it++) {
            int f = it * 256 + tid;
            int row = f >> 4, c8 = (f & 15) * 8;
            int s = q0 + row;
            uint4 v = make_uint4(0, 0, 0, 0);
            if (s < S_LEN) v = *(const uint4*)(RQh + ((size_t)s * NH + head) * HD + c8);
            *(uint4*)&Qs[row * KPH + c8] = v;
        }
    }
    __syncthreads();
    uint32_t qf[8][4];
    {
        const __half* p = smh + (warp * 16) * KPH + 2 * t;
#pragma unroll
        for (int kt = 0; kt < 8; kt++) {
            int kk = kt * 16;
            qf[kt][0] = *(const uint32_t*)(p + (g    ) * KPH + kk);
            qf[kt][1] = *(const uint32_t*)(p + (g + 8) * KPH + kk);
            qf[kt][2] = *(const uint32_t*)(p + (g    ) * KPH + kk + 8);
            qf[kt][3] = *(const uint32_t*)(p + (g + 8) * KPH + kk + 8);
        }
    }
    __syncthreads();

    auto load_kv = [&](int st, int k0) {
        __half* Ks = smh + st * ASTG;
        __half* Vs = Ks + 128 * KPH;
#pragma unroll
        for (int it = 0; it < 8; it++) {
            int f = it * 256 + tid;
            int row = f >> 4, c8 = (f & 15) * 8;
            int s = k0 + row;
            int sb = (s < S_LEN) ? 16 : 0;
            size_t off = ((size_t)(s < S_LEN ? s : S_LEN - 1) * NH + head) * HD + c8;
            cp16(Ks + row * KPH + c8, RKh + off, sb);
            cp16(Vs + row * KPH + c8, Vh + off, sb);
        }
    };

    float o_acc[16][4];
#pragma unroll
    for (int nt = 0; nt < 16; nt++)
#pragma unroll
        for (int r = 0; r < 4; r++) o_acc[nt][r] = 0.f;
    float m0 = -1e30f, m1 = -1e30f, l0 = 0.f, l1 = 0.f;
    const float scale = 0.08838834764831845f;
    const int T = (S_LEN + 127) / 128;

    load_kv(0, 0);
    CP_COMMIT();
    for (int ti = 0; ti < T; ti++) {
        CP_WAIT0();
        __syncthreads();
        if (ti + 1 < T) { load_kv((ti + 1) & 1, (ti + 1) * 128); CP_COMMIT(); }
        const __half* Ks = smh + (ti & 1) * ASTG;
        const __half* Vs = Ks + 128 * KPH;
        const int k0 = ti * 128;

        float sf[16][4];
#pragma unroll
        for (int nt = 0; nt < 16; nt++)
#pragma unroll
            for (int r = 0; r < 4; r++) sf[nt][r] = 0.f;
#pragma unroll
        for (int kt = 0; kt < 8; kt++) {
            int kk = kt * 16 + 2 * t;
#pragma unroll
            for (int nt = 0; nt < 16; nt++) {
                const __half* p = Ks + (nt * 8 + g) * KPH + kk;
                uint32_t b0 = *(const uint32_t*)(p);
                uint32_t b1 = *(const uint32_t*)(p + 8);
                mma_f16(sf[nt], qf[kt][0], qf[kt][1], qf[kt][2], qf[kt][3], b0, b1);
            }
        }
        bool edge = (k0 + 128 > S_LEN);
#pragma unroll
        for (int nt = 0; nt < 16; nt++) {
#pragma unroll
            for (int r = 0; r < 4; r++) sf[nt][r] *= scale;
            if (edge) {
                int col = k0 + nt * 8 + 2 * t;
                if (col     >= S_LEN) { sf[nt][0] = -1e30f; sf[nt][2] = -1e30f; }
                if (col + 1 >= S_LEN) { sf[nt][1] = -1e30f; sf[nt][3] = -1e30f; }
            }
        }
        float mx0 = -1e30f, mx1 = -1e30f;
#pragma unroll
        for (int nt = 0; nt < 16; nt++) {
            mx0 = fmaxf(mx0, fmaxf(sf[nt][0], sf[nt][1]));
            mx1 = fmaxf(mx1, fmaxf(sf[nt][2], sf[nt][3]));
        }
        mx0 = fmaxf(mx0, __shfl_xor_sync(0xffffffffu, mx0, 1));
        mx0 = fmaxf(mx0, __shfl_xor_sync(0xffffffffu, mx0, 2));
        mx1 = fmaxf(mx1, __shfl_xor_sync(0xffffffffu, mx1, 1));
        mx1 = fmaxf(mx1, __shfl_xor_sync(0xffffffffu, mx1, 2));
        float mn0 = fmaxf(m0, mx0), mn1 = fmaxf(m1, mx1);
        float c0 = __expf(m0 - mn0), c1 = __expf(m1 - mn1);
        float s0 = 0.f, s1 = 0.f;
#pragma unroll
        for (int nt = 0; nt < 16; nt++) {
            sf[nt][0] = __expf(sf[nt][0] - mn0);
            sf[nt][1] = __expf(sf[nt][1] - mn0);
            sf[nt][2] = __expf(sf[nt][2] - mn1);
            sf[nt][3] = __expf(sf[nt][3] - mn1);
            s0 += sf[nt][0] + sf[nt][1];
            s1 += sf[nt][2] + sf[nt][3];
        }
        s0 += __shfl_xor_sync(0xffffffffu, s0, 1);
        s0 += __shfl_xor_sync(0xffffffffu, s0, 2);
        s1 += __shfl_xor_sync(0xffffffffu, s1, 1);
        s1 += __shfl_xor_sync(0xffffffffu, s1, 2);
        l0 = l0 * c0 + s0;  l1 = l1 * c1 + s1;
        m0 = mn0;  m1 = mn1;
#pragma unroll
        for (int nt = 0; nt < 16; nt++) {
            o_acc[nt][0] *= c0; o_acc[nt][1] *= c0;
            o_acc[nt][2] *= c1; o_acc[nt][3] *= c1;
        }
        const int vr = lane & 7, vq = lane >> 3;
#pragma unroll
        for (int kt = 0; kt < 8; kt++) {
            uint32_t a0 = pack_h2(sf[2*kt  ][0], sf[2*kt  ][1]);
            uint32_t a1 = pack_h2(sf[2*kt  ][2], sf[2*kt  ][3]);
            uint32_t a2 = pack_h2(sf[2*kt+1][0], sf[2*kt+1][1]);
            uint32_t a3 = pack_h2(sf[2*kt+1][2], sf[2*kt+1][3]);
#pragma unroll
            for (int nb = 0; nb < 8; nb++) {
                const __half* vp = Vs + (kt * 16 + (vq & 1) * 8 + vr) * KPH
                                      + nb * 16 + (vq >> 1) * 8;
                uint32_t v0, v1, v2, v3;
                ldmx4t(v0, v1, v2, v3, vp);
                mma_f16(o_acc[2*nb    ], a0, a1, a2, a3, v0, v1);
                mma_f16(o_acc[2*nb + 1], a0, a1, a2, a3, v2, v3);
            }
        }
        __syncthreads();
    }

    float inv0 = 1.f / l0, inv1 = 1.f / l1;
    int s0r = q0 + warp * 16 + g;
    int s1r = s0r + 8;
#pragma unroll
    for (int nt = 0; nt < 16; nt++) {
        int col = nt * 8 + 2 * t;
        if (s0r < S_LEN)
            *(float2*)(XL + ((size_t)s0r * NH + head) * HD + col) =
                make_float2(o_acc[nt][0] * inv0, o_acc[nt][1] * inv0);
        if (s1r < S_LEN)
            *(float2*)(XL + ((size_t)s1r * NH + head) * HD + col) =
                make_float2(o_acc[nt][2] * inv1, o_acc[nt][3] * inv1);
    }
}

// ---------------- launch ----------------
extern "C" void kernel_launch(void* const* d_in, const int* in_sizes, int n_in,
                              void* d_out, int out_size) {
    const float* x    = (const float*)d_in[0];
    const float* freqs= (const float*)d_in[1];
    const float* gkm  = (const float*)d_in[2];
    const float* gkv  = (const float*)d_in[3];
    const float* Wq   = (const float*)d_in[4];
    const float* bq   = (const float*)d_in[5];
    const float* Wk   = (const float*)d_in[6];
    const float* bk   = (const float*)d_in[7];
    const float* Wv   = (const float*)d_in[8];
    const float* bv   = (const float*)d_in[9];
    const float* Wo   = (const float*)d_in[10];
    const float* bo   = (const float*)d_in[11];
    const float* gq   = (const float*)d_in[12];
    const float* gk   = (const float*)d_in[13];
    const float* Wlin = (const float*)d_in[14];
    const float* blin = (const float*)d_in[15];
    float* out = (float*)d_out;

    float *Qp, *Kp, *XLp, *Zp, *WTp, *bqkv;
    __half *xh, *Wqkvh, *Woh, *Vh, *RQh, *RKh, *XLh, *G2h;
    cudaGetSymbolAddress((void**)&Qp,   g_Q);
    cudaGetSymbolAddress((void**)&Kp,   g_K);
    cudaGetSymbolAddress((void**)&XLp,  g_XL);
    cudaGetSymbolAddress((void**)&Zp,   g_Z);
    cudaGetSymbolAddress((void**)&WTp,  g_WT);
    cudaGetSymbolAddress((void**)&bqkv, g_bqkv);
    cudaGetSymbolAddress((void**)&xh,   g_xh);
    cudaGetSymbolAddress((void**)&Wqkvh,g_Wqkvh);
    cudaGetSymbolAddress((void**)&Woh,  g_Woh);
    cudaGetSymbolAddress((void**)&Vh,   g_Vh);
    cudaGetSymbolAddress((void**)&RQh,  g_RQh);
    cudaGetSymbolAddress((void**)&RKh,  g_RKh);
    cudaGetSymbolAddress((void**)&XLh,  g_XLh);
    cudaGetSymbolAddress((void**)&G2h,  g_G2h);

    cudaFuncSetAttribute(gemm_qkv_kernel,   cudaFuncAttributeMaxDynamicSharedMemorySize, GEMM_SMEM);
    cudaFuncSetAttribute(gemm_async_kernel, cudaFuncAttributeMaxDynamicSharedMemorySize, GEMM_SMEM);
    cudaFuncSetAttribute(attn_h_kernel, cudaFuncAttributeMaxDynamicSharedMemorySize, ATT_SMEM);
    cudaFuncSetAttribute(xg_mma_kernel, cudaFuncAttributeMaxDynamicSharedMemorySize, XG_SMEM);

    // 1. conversions + weight/bias packing
    f2h_all_kernel<<<1024, 256>>>(x, Wq, Wk, Wv, Wo, bq, bk, bv, xh, Wqkvh, Woh, bqkv);
    // 2. fused QKV projection (N = 3*DIM)
    {
        dim3 grid(3 * DIM / 128, (S_LEN + 127) / 128);
        gemm_qkv_kernel<<<grid, 256, GEMM_SMEM>>>(xh, Wqkvh, bqkv, Qp, Kp, Vh);
    }
    // 3. fused rmsnorm+z+rope
    qkpost_kernel<true ><<<S_LEN, 384>>>(Qp, gq, gkm, freqs, RQh, Zp);
    qkpost_kernel<false><<<S_LEN, 384>>>(Kp, gk, nullptr, freqs, RKh, nullptr);
    // 4. G2
    transpose128_kernel<<<HD, HD>>>(Wlin, WTp);
    g2_kernel<<<NH * HD, HD>>>(gkv, WTp, G2h);
    // 5. attention
    {
        dim3 grid((S_LEN + 127) / 128, NH);
        attn_h_kernel<<<grid, 256, ATT_SMEM>>>(RQh, RKh, Vh, XLp);
    }
    // 6. xg + pack
    {
        dim3 grid((S_LEN + 127) / 128, NH);
        xg_mma_kernel<<<grid, 256, XG_SMEM>>>(RQh, G2h, Zp, blin, XLp, XLh);
    }
    // 7. output projection
    {
        dim3 grid(DIM / 128, (S_LEN + 127) / 128);
        gemm_async_kernel<<<grid, 256, GEMM_SMEM>>>(XLh, Woh, bo, out, S_LEN, DIM, DIM);
    }
}

// round 11
// speedup vs baseline: 1.0554x; 1.0046x over previous
#include <cuda_runtime.h>
#include <cuda_fp16.h>
#include <math.h>
#include <stdint.h>

#define S_LEN 4680
#define DIM 1536
#define NH 12
#define HD 128

// ---------------- static scratch ----------------
__device__ float  g_Q  [S_LEN*DIM];
__device__ float  g_K  [S_LEN*DIM];
__device__ float  g_Z  [S_LEN*NH];
__device__ float  g_WT [HD*HD];
__device__ float  g_bqkv[3*DIM];
__device__ __half g_xh [S_LEN*DIM];
__device__ __half g_Wqkvh[3*DIM*DIM];   // Wq | Wk | Wv
__device__ __half g_Woh[DIM*DIM];
__device__ __half g_Vh [S_LEN*DIM];
__device__ __half g_RQh[S_LEN*DIM];
__device__ __half g_RKh[S_LEN*DIM];
__device__ __half g_XLh[S_LEN*DIM];
__device__ __half g_G2h[NH*HD*HD];   // [n][j][d]

// ---------------- helpers ----------------
__device__ __forceinline__ uint32_t pack_h2(float lo, float hi) {
    __half2 h = __floats2half2_rn(lo, hi);
    return *reinterpret_cast<uint32_t*>(&h);
}
__device__ __forceinline__ void mma_f16(float c[4],
                                        uint32_t a0, uint32_t a1, uint32_t a2, uint32_t a3,
                                        uint32_t b0, uint32_t b1) {
    asm("mma.sync.aligned.m16n8k16.row.col.f32.f16.f16.f32 "
        "{%0,%1,%2,%3},{%4,%5,%6,%7},{%8,%9},{%0,%1,%2,%3};"
        : "+f"(c[0]), "+f"(c[1]), "+f"(c[2]), "+f"(c[3])
        : "r"(a0), "r"(a1), "r"(a2), "r"(a3), "r"(b0), "r"(b1));
}
__device__ __forceinline__ void ldmx4t(uint32_t &r0, uint32_t &r1, uint32_t &r2, uint32_t &r3,
                                       const __half* p) {
    uint32_t addr = (uint32_t)__cvta_generic_to_shared(p);
    asm volatile("ldmatrix.sync.aligned.m8n8.x4.trans.shared.b16 {%0,%1,%2,%3},[%4];"
                 : "=r"(r0), "=r"(r1), "=r"(r2), "=r"(r3) : "r"(addr));
}
__device__ __forceinline__ void cp16(__half* dst, const __half* src, int src_bytes) {
    uint32_t d = (uint32_t)__cvta_generic_to_shared(dst);
    asm volatile("cp.async.cg.shared.global [%0], [%1], 16, %2;"
                 :: "r"(d), "l"(src), "r"(src_bytes));
}
#define CP_COMMIT() asm volatile("cp.async.commit_group;")
#define CP_WAIT0()  asm volatile("cp.async.wait_group 0;")

// ---------------- batched convert: x + 4 weights -> fp16, biases -> concat ----------------
__global__ void f2h_all_kernel(const float* __restrict__ x,
                               const float* __restrict__ w0, const float* __restrict__ w1,
                               const float* __restrict__ w2, const float* __restrict__ w3,
                               const float* __restrict__ bq, const float* __restrict__ bk,
                               const float* __restrict__ bv,
                               __half* __restrict__ xh, __half* __restrict__ wqkv,
                               __half* __restrict__ woh, float* __restrict__ bqkv) {
    const int NX = S_LEN * DIM / 4, NW = DIM * DIM / 4, NB = DIM / 4;
    const int total = NX + 4 * NW + 3 * NB;
    for (int i = blockIdx.x * blockDim.x + threadIdx.x; i < total; i += gridDim.x * blockDim.x) {
        int j = i;
        if (j < NX + 4 * NW) {
            const float* src; __half* dst;
            if (j < NX) { src = x; dst = xh; }
            else {
                j -= NX;
                int seg = j / NW; j -= seg * NW;
                src = (seg == 0) ? w0 : (seg == 1) ? w1 : (seg == 2) ? w2 : w3;
                dst = (seg == 3) ? woh : wqkv + (size_t)seg * DIM * DIM;
            }
            float4 v = ((const float4*)src)[j];
            ((uint2*)dst)[j] = make_uint2(pack_h2(v.x, v.y), pack_h2(v.z, v.w));
        } else {
            j -= NX + 4 * NW;
            int seg = j / NB; j -= seg * NB;
            const float* src = (seg == 0) ? bq : (seg == 1) ? bk : bv;
            ((float4*)bqkv)[seg * NB + j] = ((const float4*)src)[j];
        }
    }
}

// ---------------- GEMM config (256 thr, 8 warps, 2-stage) ----------------
#define GKP 72
#define GSTG (2 * 128 * GKP)
#define GEMM_SMEM (2 * GSTG * 2)

// ---------------- fused QKV GEMM: N = 3*DIM, epilogue routes per segment ----------------
__global__ __launch_bounds__(256, 2) void gemm_qkv_kernel(
    const __half* __restrict__ A, const __half* __restrict__ W,
    const float* __restrict__ bqkv,
    float* __restrict__ Qo, float* __restrict__ Ko, __half* __restrict__ Vo) {
    extern __shared__ __half gsm[];
    const int M = S_LEN, K = DIM;
    const int tid = threadIdx.x;
    const int warp = tid >> 5, lane = tid & 31;
    const int g = lane >> 2, t = lane & 3;
    const int wm = warp >> 2, wn = warp & 3;
    const int bm = blockIdx.y * 128, bn = blockIdx.x * 128;

    float acc[4][4][4];
#pragma unroll
    for (int i = 0; i < 4; i++)
#pragma unroll
        for (int j = 0; j < 4; j++)
#pragma unroll
            for (int r = 0; r < 4; r++) acc[i][j][r] = 0.f;

    auto load_stage = [&](int s, int k0) {
        __half* As = gsm + s * GSTG;
        __half* Bs = As + 128 * GKP;
#pragma unroll
        for (int it = 0; it < 4; it++) {
            int f = it * 256 + tid;
            int row = f >> 3, c8 = (f & 7) * 8;
            int gm = bm + row;
            const __half* sa = A + (size_t)(gm < M ? gm : M - 1) * K + k0 + c8;
            cp16(As + row * GKP + c8, sa, gm < M ? 16 : 0);
            const __half* sb = W + (size_t)(bn + row) * K + k0 + c8;
            cp16(Bs + row * GKP + c8, sb, 16);
        }
    };

    const int nT = K / 64;
    load_stage(0, 0);
    CP_COMMIT();
    for (int i = 0; i < nT; i++) {
        CP_WAIT0();
        __syncthreads();
        if (i + 1 < nT) { load_stage((i + 1) & 1, (i + 1) * 64); CP_COMMIT(); }
        const __half* As = gsm + (i & 1) * GSTG;
        const __half* Bs = As + 128 * GKP;
#pragma unroll
        for (int ks = 0; ks < 4; ks++) {
            int kk = ks * 16;
            uint32_t af[4][4], bf[4][2];
#pragma unroll
            for (int mt = 0; mt < 4; mt++) {
                const __half* p = As + (wm * 64 + mt * 16) * GKP + kk + 2 * t;
                af[mt][0] = *(const uint32_t*)(p + (g    ) * GKP);
                af[mt][1] = *(const uint32_t*)(p + (g + 8) * GKP);
                af[mt][2] = *(const uint32_t*)(p + (g    ) * GKP + 8);
                af[mt][3] = *(const uint32_t*)(p + (g + 8) * GKP + 8);
            }
#pragma unroll
            for (int nt = 0; nt < 4; nt++) {
                const __half* p = Bs + (wn * 32 + nt * 8 + g) * GKP + kk + 2 * t;
                bf[nt][0] = *(const uint32_t*)(p);
                bf[nt][1] = *(const uint32_t*)(p + 8);
            }
#pragma unroll
            for (int mt = 0; mt < 4; mt++)
#pragma unroll
                for (int nt = 0; nt < 4; nt++)
                    mma_f16(acc[mt][nt], af[mt][0], af[mt][1], af[mt][2], af[mt][3],
                            bf[nt][0], bf[nt][1]);
        }
        __syncthreads();
    }
    const int seg = bn / DIM;
    const int colbase = bn - seg * DIM;
    const float* bias = bqkv + seg * DIM;
#pragma unroll
    for (int mt = 0; mt < 4; mt++) {
#pragma unroll
        for (int nt = 0; nt < 4; nt++) {
            int col = colbase + wn * 32 + nt * 8 + 2 * t;
            float2 b2 = *(const float2*)(bias + col);
            int r0 = bm + wm * 64 + mt * 16 + g;
            int r1 = r0 + 8;
            float v00 = acc[mt][nt][0] + b2.x, v01 = acc[mt][nt][1] + b2.y;
            float v10 = acc[mt][nt][2] + b2.x, v11 = acc[mt][nt][3] + b2.y;
            if (seg == 2) {
                if (r0 < M) *(uint32_t*)(Vo + (size_t)r0 * DIM + col) = pack_h2(v00, v01);
                if (r1 < M) *(uint32_t*)(Vo + (size_t)r1 * DIM + col) = pack_h2(v10, v11);
            } else {
                float* C = (seg == 0) ? Qo : Ko;
                if (r0 < M) *(float2*)(C + (size_t)r0 * DIM + col) = make_float2(v00, v01);
                if (r1 < M) *(float2*)(C + (size_t)r1 * DIM + col) = make_float2(v10, v11);
            }
        }
    }
}

// ---------------- out projection GEMM ----------------
__global__ __launch_bounds__(256, 2) void gemm_async_kernel(
    const __half* __restrict__ A, const __half* __restrict__ W,
    const float* __restrict__ bias, float* __restrict__ C,
    int M, int N, int K) {
    extern __shared__ __half gsm[];
    const int tid = threadIdx.x;
    const int warp = tid >> 5, lane = tid & 31;
    const int g = lane >> 2, t = lane & 3;
    const int wm = warp >> 2, wn = warp & 3;
    const int bm = blockIdx.y * 128, bn = blockIdx.x * 128;

    float acc[4][4][4];
#pragma unroll
    for (int i = 0; i < 4; i++)
#pragma unroll
        for (int j = 0; j < 4; j++)
#pragma unroll
            for (int r = 0; r < 4; r++) acc[i][j][r] = 0.f;

    auto load_stage = [&](int s, int k0) {
        __half* As = gsm + s * GSTG;
        __half* Bs = As + 128 * GKP;
#pragma unroll
        for (int it = 0; it < 4; it++) {
            int f = it * 256 + tid;
            int row = f >> 3, c8 = (f & 7) * 8;
            int gm = bm + row;
            const __half* sa = A + (size_t)(gm < M ? gm : M - 1) * K + k0 + c8;
            cp16(As + row * GKP + c8, sa, gm < M ? 16 : 0);
            const __half* sb = W + (size_t)(bn + row) * K + k0 + c8;
            cp16(Bs + row * GKP + c8, sb, 16);
        }
    };

    const int nT = K / 64;
    load_stage(0, 0);
    CP_COMMIT();
    for (int i = 0; i < nT; i++) {
        CP_WAIT0();
        __syncthreads();
        if (i + 1 < nT) { load_stage((i + 1) & 1, (i + 1) * 64); CP_COMMIT(); }
        const __half* As = gsm + (i & 1) * GSTG;
        const __half* Bs = As + 128 * GKP;
#pragma unroll
        for (int ks = 0; ks < 4; ks++) {
            int kk = ks * 16;
            uint32_t af[4][4], bf[4][2];
#pragma unroll
            for (int mt = 0; mt < 4; mt++) {
                const __half* p = As + (wm * 64 + mt * 16) * GKP + kk + 2 * t;
                af[mt][0] = *(const uint32_t*)(p + (g    ) * GKP);
                af[mt][1] = *(const uint32_t*)(p + (g + 8) * GKP);
                af[mt][2] = *(const uint32_t*)(p + (g    ) * GKP + 8);
                af[mt][3] = *(const uint32_t*)(p + (g + 8) * GKP + 8);
            }
#pragma unroll
            for (int nt = 0; nt < 4; nt++) {
                const __half* p = Bs + (wn * 32 + nt * 8 + g) * GKP + kk + 2 * t;
                bf[nt][0] = *(const uint32_t*)(p);
                bf[nt][1] = *(const uint32_t*)(p + 8);
            }
#pragma unroll
            for (int mt = 0; mt < 4; mt++)
#pragma unroll
                for (int nt = 0; nt < 4; nt++)
                    mma_f16(acc[mt][nt], af[mt][0], af[mt][1], af[mt][2], af[mt][3],
                            bf[nt][0], bf[nt][1]);
        }
        __syncthreads();
    }
#pragma unroll
    for (int mt = 0; mt < 4; mt++) {
#pragma unroll
        for (int nt = 0; nt < 4; nt++) {
            int col = bn + wn * 32 + nt * 8 + 2 * t;
            float2 b2 = *(const float2*)(bias + col);
            int r0 = bm + wm * 64 + mt * 16 + g;
            int r1 = r0 + 8;
            if (r0 < M)
                *(float2*)(C + (size_t)r0 * N + col) =
                    make_float2(acc[mt][nt][0] + b2.x, acc[mt][nt][1] + b2.y);
            if (r1 < M)
                *(float2*)(C + (size_t)r1 * N + col) =
                    make_float2(acc[mt][nt][2] + b2.x, acc[mt][nt][3] + b2.y);
        }
    }
}

// ---------------- fused rmsnorm (+z) + rope -> fp16; blockIdx.y: 0=Q(z) 1=K ----------------
__global__ __launch_bounds__(384) void qkpost_kernel(
    const float* __restrict__ Qf, const float* __restrict__ Kf,
    const float* __restrict__ gq, const float* __restrict__ gk,
    const float* __restrict__ gkm, const float* __restrict__ freqs,
    __half* __restrict__ RQh, __half* __restrict__ RKh, float* __restrict__ Z) {
    __shared__ float vals[DIM];
    __shared__ float red[12];
    __shared__ float s_scale;
    const bool isQ = (blockIdx.y == 0);
    const float* X  = isQ ? Qf : Kf;
    const float* gw = isQ ? gq : gk;
    __half* Yh      = isQ ? RQh : RKh;
    const int s = blockIdx.x;
    const int tid = threadIdx.x;
    const int lane = tid & 31, wid = tid >> 5;
    const float* x = X + (size_t)s * DIM;

    float ss = 0.f;
#pragma unroll
    for (int k = 0; k < 4; k++) {
        int i = tid + k * 384;
        float v = x[i];
        vals[i] = v;
        ss += v * v;
    }
#pragma unroll
    for (int o = 16; o > 0; o >>= 1) ss += __shfl_xor_sync(0xffffffffu, ss, o);
    if (lane == 0) red[wid] = ss;
    __syncthreads();
    if (wid == 0) {
        float v = (lane < 12) ? red[lane] : 0.f;
#pragma unroll
        for (int o = 8; o > 0; o >>= 1) v += __shfl_xor_sync(0xffffffffu, v, o);
        if (lane == 0) s_scale = rsqrtf(v / (float)DIM + 1e-6f);
    }
    __syncthreads();
    const float sc = s_scale;
#pragma unroll
    for (int k = 0; k < 4; k++) {
        int i = tid + k * 384;
        vals[i] = vals[i] * sc * gw[i];
    }
    __syncthreads();
    if (isQ) {
        const float* vh = vals + wid * HD;
        float sum = 0.f;
#pragma unroll
        for (int k = 0; k < 4; k++) {
            int d = lane + k * 32;
            sum += fmaxf(vh[d], 0.f) * gkm[wid * HD + d];
        }
#pragma unroll
        for (int o = 16; o > 0; o >>= 1) sum += __shfl_xor_sync(0xffffffffu, sum, o);
        if (lane == 0) Z[s * NH + wid] = 1.f / (sum + 1e-6f);
    }
    const int w = s % 52, h = (s / 52) % 30, f = s / (52 * 30);
#pragma unroll
    for (int k = 0; k < 2; k++) {
        int p = tid + k * 384;
        int i = p & 63;
        int pos = (i < 22) ? f : (i < 43) ? h : w;
        float cr = freqs[(pos * 64 + i) * 2 + 0];
        float ci = freqs[(pos * 64 + i) * 2 + 1];
        float xr = vals[2 * p], xi = vals[2 * p + 1];
        *(uint32_t*)(Yh + (size_t)s * DIM + 2 * p) =
            pack_h2(xr * cr - xi * ci, xr * ci + xi * cr);
    }
}

// ---------------- Wlin transpose ----------------
__global__ void transpose128_kernel(const float* __restrict__ in, float* __restrict__ out) {
    int j = blockIdx.x, m = threadIdx.x;
    out[m * HD + j] = in[j * HD + m];
}

// ---------------- G2h[n][j][d] ----------------
__global__ void g2_kernel(const float* __restrict__ gkv, const float* __restrict__ WT,
                          __half* __restrict__ G2h) {
    int nd = blockIdx.x;
    int n = nd >> 7, d = nd & 127;
    __shared__ float kv[HD];
    kv[threadIdx.x] = gkv[(size_t)nd * HD + threadIdx.x];
    __syncthreads();
    int j = threadIdx.x;
    float sum = 0.f;
#pragma unroll 8
    for (int m = 0; m < HD; m++) sum += kv[m] * WT[m * HD + j];
    G2h[((size_t)n * HD + j) * HD + d] = __float2half(sum);
}

// ---------------- FP16 flash attention + fused xg epilogue, Bc=128, 2-stage ----------------
#define KPH 136
#define ASTG (2 * 128 * KPH)
#define ATT_SMEM (2 * ASTG * 2)
__global__ __launch_bounds__(256, 1) void attn_h_kernel(
    const __half* __restrict__ RQh, const __half* __restrict__ RKh,
    const __half* __restrict__ Vh, const __half* __restrict__ G2h,
    const float* __restrict__ Z, const float* __restrict__ blin,
    __half* __restrict__ XLh) {
    extern __shared__ __half smh[];
    const int tid = threadIdx.x;
    const int warp = tid >> 5, lane = tid & 31;
    const int g = lane >> 2, t = lane & 3;
    const int head = blockIdx.y;
    const int q0 = blockIdx.x * 128;

    {
        __half* Qs = smh;
#pragma unroll
        for (int it = 0; it < 8; it++) {
            int f = it * 256 + tid;
            int row = f >> 4, c8 = (f & 15) * 8;
            int s = q0 + row;
            uint4 v = make_uint4(0, 0, 0, 0);
            if (s < S_LEN) v = *(const uint4*)(RQh + ((size_t)s * NH + head) * HD + c8);
            *(uint4*)&Qs[row * KPH + c8] = v;
        }
    }
    __syncthreads();
    uint32_t qf[8][4];
    {
        const __half* p = smh + (warp * 16) * KPH + 2 * t;
#pragma unroll
        for (int kt = 0; kt < 8; kt++) {
            int kk = kt * 16;
            qf[kt][0] = *(const uint32_t*)(p + (g    ) * KPH + kk);
            qf[kt][1] = *(const uint32_t*)(p + (g + 8) * KPH + kk);
            qf[kt][2] = *(const uint32_t*)(p + (g    ) * KPH + kk + 8);
            qf[kt][3] = *(const uint32_t*)(p + (g + 8) * KPH + kk + 8);
        }
    }
    __syncthreads();

    auto load_kv = [&](int st, int k0) {
        __half* Ks = smh + st * ASTG;
        __half* Vs = Ks + 128 * KPH;
#pragma unroll
        for (int it = 0; it < 8; it++) {
            int f = it * 256 + tid;
            int row = f >> 4, c8 = (f & 15) * 8;
            int s = k0 + row;
            int sb = (s < S_LEN) ? 16 : 0;
            size_t off = ((size_t)(s < S_LEN ? s : S_LEN - 1) * NH + head) * HD + c8;
            cp16(Ks + row * KPH + c8, RKh + off, sb);
            cp16(Vs + row * KPH + c8, Vh + off, sb);
        }
    };

    float o_acc[16][4];
#pragma unroll
    for (int nt = 0; nt < 16; nt++)
#pragma unroll
        for (int r = 0; r < 4; r++) o_acc[nt][r] = 0.f;
    float m0 = -1e30f, m1 = -1e30f, l0 = 0.f, l1 = 0.f;
    const float scale = 0.08838834764831845f;
    const int T = (S_LEN + 127) / 128;

    float sf[16][4];
    load_kv(0, 0);
    CP_COMMIT();
    for (int ti = 0; ti < T; ti++) {
        CP_WAIT0();
        __syncthreads();
        if (ti + 1 < T) { load_kv((ti + 1) & 1, (ti + 1) * 128); CP_COMMIT(); }
        const __half* Ks = smh + (ti & 1) * ASTG;
        const __half* Vs = Ks + 128 * KPH;
        const int k0 = ti * 128;

#pragma unroll
        for (int nt = 0; nt < 16; nt++)
#pragma unroll
            for (int r = 0; r < 4; r++) sf[nt][r] = 0.f;
#pragma unroll
        for (int kt = 0; kt < 8; kt++) {
            int kk = kt * 16 + 2 * t;
#pragma unroll
            for (int nt = 0; nt < 16; nt++) {
                const __half* p = Ks + (nt * 8 + g) * KPH + kk;
                uint32_t b0 = *(const uint32_t*)(p);
                uint32_t b1 = *(const uint32_t*)(p + 8);
                mma_f16(sf[nt], qf[kt][0], qf[kt][1], qf[kt][2], qf[kt][3], b0, b1);
            }
        }
        bool edge = (k0 + 128 > S_LEN);
#pragma unroll
        for (int nt = 0; nt < 16; nt++) {
#pragma unroll
            for (int r = 0; r < 4; r++) sf[nt][r] *= scale;
            if (edge) {
                int col = k0 + nt * 8 + 2 * t;
                if (col     >= S_LEN) { sf[nt][0] = -1e30f; sf[nt][2] = -1e30f; }
                if (col + 1 >= S_LEN) { sf[nt][1] = -1e30f; sf[nt][3] = -1e30f; }
            }
        }
        float mx0 = -1e30f, mx1 = -1e30f;
#pragma unroll
        for (int nt = 0; nt < 16; nt++) {
            mx0 = fmaxf(mx0, fmaxf(sf[nt][0], sf[nt][1]));
            mx1 = fmaxf(mx1, fmaxf(sf[nt][2], sf[nt][3]));
        }
        mx0 = fmaxf(mx0, __shfl_xor_sync(0xffffffffu, mx0, 1));
        mx0 = fmaxf(mx0, __shfl_xor_sync(0xffffffffu, mx0, 2));
        mx1 = fmaxf(mx1, __shfl_xor_sync(0xffffffffu, mx1, 1));
        mx1 = fmaxf(mx1, __shfl_xor_sync(0xffffffffu, mx1, 2));
        float mn0 = fmaxf(m0, mx0), mn1 = fmaxf(m1, mx1);
        float c0 = __expf(m0 - mn0), c1 = __expf(m1 - mn1);
        float s0 = 0.f, s1 = 0.f;
#pragma unroll
        for (int nt = 0; nt < 16; nt++) {
            sf[nt][0] = __expf(sf[nt][0] - mn0);
            sf[nt][1] = __expf(sf[nt][1] - mn0);
            sf[nt][2] = __expf(sf[nt][2] - mn1);
            sf[nt][3] = __expf(sf[nt][3] - mn1);
            s0 += sf[nt][0] + sf[nt][1];
            s1 += sf[nt][2] + sf[nt][3];
        }
        s0 += __shfl_xor_sync(0xffffffffu, s0, 1);
        s0 += __shfl_xor_sync(0xffffffffu, s0, 2);
        s1 += __shfl_xor_sync(0xffffffffu, s1, 1);
        s1 += __shfl_xor_sync(0xffffffffu, s1, 2);
        l0 = l0 * c0 + s0;  l1 = l1 * c1 + s1;
        m0 = mn0;  m1 = mn1;
#pragma unroll
        for (int nt = 0; nt < 16; nt++) {
            o_acc[nt][0] *= c0; o_acc[nt][1] *= c0;
            o_acc[nt][2] *= c1; o_acc[nt][3] *= c1;
        }
        const int vr = lane & 7, vq = lane >> 3;
#pragma unroll
        for (int kt = 0; kt < 8; kt++) {
            uint32_t a0 = pack_h2(sf[2*kt  ][0], sf[2*kt  ][1]);
            uint32_t a1 = pack_h2(sf[2*kt  ][2], sf[2*kt  ][3]);
            uint32_t a2 = pack_h2(sf[2*kt+1][0], sf[2*kt+1][1]);
            uint32_t a3 = pack_h2(sf[2*kt+1][2], sf[2*kt+1][3]);
#pragma unroll
            for (int nb = 0; nb < 8; nb++) {
                const __half* vp = Vs + (kt * 16 + (vq & 1) * 8 + vr) * KPH
                                      + nb * 16 + (vq >> 1) * 8;
                uint32_t v0, v1, v2, v3;
                ldmx4t(v0, v1, v2, v3, vp);
                mma_f16(o_acc[2*nb    ], a0, a1, a2, a3, v0, v1);
                mma_f16(o_acc[2*nb + 1], a0, a1, a2, a3, v2, v3);
            }
        }
        __syncthreads();
    }

    // ---- fused xg: load G2[head] into stage-0 smem, MMAs into (dead) sf ----
    {
        __half* G2s = smh;
#pragma unroll
        for (int it = 0; it < 8; it++) {
            int f = it * 256 + tid;
            int row = f >> 4, c8 = (f & 15) * 8;
            uint4 gv = *(const uint4*)(G2h + ((size_t)head * HD + row) * HD + c8);
            *(uint4*)&G2s[row * KPH + c8] = gv;
        }
        __syncthreads();
#pragma unroll
        for (int nt = 0; nt < 16; nt++)
#pragma unroll
            for (int r = 0; r < 4; r++) sf[nt][r] = 0.f;
#pragma unroll
        for (int kt = 0; kt < 8; kt++) {
            int kk = kt * 16 + 2 * t;
#pragma unroll
            for (int nt = 0; nt < 16; nt++) {
                const __half* p = G2s + (nt * 8 + g) * KPH + kk;
                uint32_t b0 = *(const uint32_t*)(p);
                uint32_t b1 = *(const uint32_t*)(p + 8);
                mma_f16(sf[nt], qf[kt][0], qf[kt][1], qf[kt][2], qf[kt][3], b0, b1);
            }
        }
    }

    // ---- combined epilogue: XLh = half(o/l + z*xg + blin) ----
    float inv0 = 1.f / l0, inv1 = 1.f / l1;
    int s0r = q0 + warp * 16 + g;
    int s1r = s0r + 8;
    float z0 = (s0r < S_LEN) ? Z[s0r * NH + head] : 0.f;
    float z1 = (s1r < S_LEN) ? Z[s1r * NH + head] : 0.f;
#pragma unroll
    for (int nt = 0; nt < 16; nt++) {
        int col = nt * 8 + 2 * t;
        float2 bl = *(const float2*)(blin + col);
        if (s0r < S_LEN) {
            float v0 = o_acc[nt][0] * inv0 + sf[nt][0] * z0 + bl.x;
            float v1 = o_acc[nt][1] * inv0 + sf[nt][1] * z0 + bl.y;
            *(uint32_t*)(XLh + ((size_t)s0r * NH + head) * HD + col) = pack_h2(v0, v1);
        }
        if (s1r < S_LEN) {
            float v0 = o_acc[nt][2] * inv1 + sf[nt][2] * z1 + bl.x;
            float v1 = o_acc[nt][3] * inv1 + sf[nt][3] * z1 + bl.y;
            *(uint32_t*)(XLh + ((size_t)s1r * NH + head) * HD + col) = pack_h2(v0, v1);
        }
    }
}

// ---------------- launch ----------------
extern "C" void kernel_launch(void* const* d_in, const int* in_sizes, int n_in,
                              void* d_out, int out_size) {
    const float* x    = (const float*)d_in[0];
    const float* freqs= (const float*)d_in[1];
    const float* gkm  = (const float*)d_in[2];
    const float* gkv  = (const float*)d_in[3];
    const float* Wq   = (const float*)d_in[4];
    const float* bq   = (const float*)d_in[5];
    const float* Wk   = (const float*)d_in[6];
    const float* bk   = (const float*)d_in[7];
    const float* Wv   = (const float*)d_in[8];
    const float* bv   = (const float*)d_in[9];
    const float* Wo   = (const float*)d_in[10];
    const float* bo   = (const float*)d_in[11];
    const float* gq   = (const float*)d_in[12];
    const float* gk   = (const float*)d_in[13];
    const float* Wlin = (const float*)d_in[14];
    const float* blin = (const float*)d_in[15];
    float* out = (float*)d_out;

    float *Qp, *Kp, *Zp, *WTp, *bqkv;
    __half *xh, *Wqkvh, *Woh, *Vh, *RQh, *RKh, *XLh, *G2h;
    cudaGetSymbolAddress((void**)&Qp,   g_Q);
    cudaGetSymbolAddress((void**)&Kp,   g_K);
    cudaGetSymbolAddress((void**)&Zp,   g_Z);
    cudaGetSymbolAddress((void**)&WTp,  g_WT);
    cudaGetSymbolAddress((void**)&bqkv, g_bqkv);
    cudaGetSymbolAddress((void**)&xh,   g_xh);
    cudaGetSymbolAddress((void**)&Wqkvh,g_Wqkvh);
    cudaGetSymbolAddress((void**)&Woh,  g_Woh);
    cudaGetSymbolAddress((void**)&Vh,   g_Vh);
    cudaGetSymbolAddress((void**)&RQh,  g_RQh);
    cudaGetSymbolAddress((void**)&RKh,  g_RKh);
    cudaGetSymbolAddress((void**)&XLh,  g_XLh);
    cudaGetSymbolAddress((void**)&G2h,  g_G2h);

    cudaFuncSetAttribute(gemm_qkv_kernel,   cudaFuncAttributeMaxDynamicSharedMemorySize, GEMM_SMEM);
    cudaFuncSetAttribute(gemm_async_kernel, cudaFuncAttributeMaxDynamicSharedMemorySize, GEMM_SMEM);
    cudaFuncSetAttribute(attn_h_kernel, cudaFuncAttributeMaxDynamicSharedMemorySize, ATT_SMEM);

    // 1. conversions + packing
    f2h_all_kernel<<<1024, 256>>>(x, Wq, Wk, Wv, Wo, bq, bk, bv, xh, Wqkvh, Woh, bqkv);
    // 2. fused QKV projection
    {
        dim3 grid(3 * DIM / 128, (S_LEN + 127) / 128);
        gemm_qkv_kernel<<<grid, 256, GEMM_SMEM>>>(xh, Wqkvh, bqkv, Qp, Kp, Vh);
    }
    // 3. fused rmsnorm+z+rope (Q and K in one launch)
    {
        dim3 grid(S_LEN, 2);
        qkpost_kernel<<<grid, 384>>>(Qp, Kp, gq, gk, gkm, freqs, RQh, RKh, Zp);
    }
    // 4. G2
    transpose128_kernel<<<HD, HD>>>(Wlin, WTp);
    g2_kernel<<<NH * HD, HD>>>(gkv, WTp, G2h);
    // 5. attention + fused xg -> XLh
    {
        dim3 grid((S_LEN + 127) / 128, NH);
        attn_h_kernel<<<grid, 256, ATT_SMEM>>>(RQh, RKh, Vh, G2h, Zp, blin, XLh);
    }
    // 6. output projection
    {
        dim3 grid(DIM / 128, (S_LEN + 127) / 128);
        gemm_async_kernel<<<grid, 256, GEMM_SMEM>>>(XLh, Woh, bo, out, S_LEN, DIM, DIM);
    }
}

// round 12
// speedup vs baseline: 1.0751x; 1.0187x over previous
#include <cuda_runtime.h>
#include <cuda_fp16.h>
#include <math.h>
#include <stdint.h>

#define S_LEN 4680
#define DIM 1536
#define NH 12
#define HD 128

// ---------------- static scratch ----------------
__device__ float  g_Q  [S_LEN*DIM];
__device__ float  g_K  [S_LEN*DIM];
__device__ float  g_Z  [S_LEN*NH];
__device__ float  g_WT [HD*HD];
__device__ float  g_bqkv[3*DIM];
__device__ __half g_xh [S_LEN*DIM];
__device__ __half g_Wqkvh[3*DIM*DIM];   // Wq | Wk | Wv
__device__ __half g_Woh[DIM*DIM];
__device__ __half g_Vh [S_LEN*DIM];
__device__ __half g_RQh[S_LEN*DIM];
__device__ __half g_RKh[S_LEN*DIM];
__device__ __half g_XLh[S_LEN*DIM];
__device__ __half g_G2h[NH*HD*HD];   // [n][j][d]

// ---------------- helpers ----------------
__device__ __forceinline__ uint32_t pack_h2(float lo, float hi) {
    __half2 h = __floats2half2_rn(lo, hi);
    return *reinterpret_cast<uint32_t*>(&h);
}
__device__ __forceinline__ float ex2f(float x) {
    float r;
    asm("ex2.approx.f32 %0, %1;" : "=f"(r) : "f"(x));
    return r;
}
__device__ __forceinline__ void mma_f16(float c[4],
                                        uint32_t a0, uint32_t a1, uint32_t a2, uint32_t a3,
                                        uint32_t b0, uint32_t b1) {
    asm("mma.sync.aligned.m16n8k16.row.col.f32.f16.f16.f32 "
        "{%0,%1,%2,%3},{%4,%5,%6,%7},{%8,%9},{%0,%1,%2,%3};"
        : "+f"(c[0]), "+f"(c[1]), "+f"(c[2]), "+f"(c[3])
        : "r"(a0), "r"(a1), "r"(a2), "r"(a3), "r"(b0), "r"(b1));
}
__device__ __forceinline__ void ldmx4t(uint32_t &r0, uint32_t &r1, uint32_t &r2, uint32_t &r3,
                                       const __half* p) {
    uint32_t addr = (uint32_t)__cvta_generic_to_shared(p);
    asm volatile("ldmatrix.sync.aligned.m8n8.x4.trans.shared.b16 {%0,%1,%2,%3},[%4];"
                 : "=r"(r0), "=r"(r1), "=r"(r2), "=r"(r3) : "r"(addr));
}
__device__ __forceinline__ void cp16(__half* dst, const __half* src, int src_bytes) {
    uint32_t d = (uint32_t)__cvta_generic_to_shared(dst);
    asm volatile("cp.async.cg.shared.global [%0], [%1], 16, %2;"
                 :: "r"(d), "l"(src), "r"(src_bytes));
}
#define CP_COMMIT() asm volatile("cp.async.commit_group;")
#define CP_WAIT0()  asm volatile("cp.async.wait_group 0;")

// scale * log2(e): folded into Q fragments for base-2 softmax
#define QSCALE 0.12751879523595848f     // 128^-0.5 * 1.4426950408889634
#define INV_QSCALE 7.841968912587944f   // 1 / QSCALE

// ---------------- batched convert: x + 4 weights -> fp16, biases -> concat ----------------
__global__ void f2h_all_kernel(const float* __restrict__ x,
                               const float* __restrict__ w0, const float* __restrict__ w1,
                               const float* __restrict__ w2, const float* __restrict__ w3,
                               const float* __restrict__ bq, const float* __restrict__ bk,
                               const float* __restrict__ bv,
                               __half* __restrict__ xh, __half* __restrict__ wqkv,
                               __half* __restrict__ woh, float* __restrict__ bqkv) {
    const int NX = S_LEN * DIM / 4, NW = DIM * DIM / 4, NB = DIM / 4;
    const int total = NX + 4 * NW + 3 * NB;
    for (int i = blockIdx.x * blockDim.x + threadIdx.x; i < total; i += gridDim.x * blockDim.x) {
        int j = i;
        if (j < NX + 4 * NW) {
            const float* src; __half* dst;
            if (j < NX) { src = x; dst = xh; }
            else {
                j -= NX;
                int seg = j / NW; j -= seg * NW;
                src = (seg == 0) ? w0 : (seg == 1) ? w1 : (seg == 2) ? w2 : w3;
                dst = (seg == 3) ? woh : wqkv + (size_t)seg * DIM * DIM;
            }
            float4 v = ((const float4*)src)[j];
            ((uint2*)dst)[j] = make_uint2(pack_h2(v.x, v.y), pack_h2(v.z, v.w));
        } else {
            j -= NX + 4 * NW;
            int seg = j / NB; j -= seg * NB;
            const float* src = (seg == 0) ? bq : (seg == 1) ? bk : bv;
            ((float4*)bqkv)[seg * NB + j] = ((const float4*)src)[j];
        }
    }
}

// ---------------- GEMM config (256 thr, 8 warps, 2-stage) ----------------
#define GKP 72
#define GSTG (2 * 128 * GKP)
#define GEMM_SMEM (2 * GSTG * 2)

// ---------------- fused QKV GEMM: N = 3*DIM, epilogue routes per segment ----------------
__global__ __launch_bounds__(256, 2) void gemm_qkv_kernel(
    const __half* __restrict__ A, const __half* __restrict__ W,
    const float* __restrict__ bqkv,
    float* __restrict__ Qo, float* __restrict__ Ko, __half* __restrict__ Vo) {
    extern __shared__ __half gsm[];
    const int M = S_LEN, K = DIM;
    const int tid = threadIdx.x;
    const int warp = tid >> 5, lane = tid & 31;
    const int g = lane >> 2, t = lane & 3;
    const int wm = warp >> 2, wn = warp & 3;
    const int bm = blockIdx.y * 128, bn = blockIdx.x * 128;

    float acc[4][4][4];
#pragma unroll
    for (int i = 0; i < 4; i++)
#pragma unroll
        for (int j = 0; j < 4; j++)
#pragma unroll
            for (int r = 0; r < 4; r++) acc[i][j][r] = 0.f;

    auto load_stage = [&](int s, int k0) {
        __half* As = gsm + s * GSTG;
        __half* Bs = As + 128 * GKP;
#pragma unroll
        for (int it = 0; it < 4; it++) {
            int f = it * 256 + tid;
            int row = f >> 3, c8 = (f & 7) * 8;
            int gm = bm + row;
            const __half* sa = A + (size_t)(gm < M ? gm : M - 1) * K + k0 + c8;
            cp16(As + row * GKP + c8, sa, gm < M ? 16 : 0);
            const __half* sb = W + (size_t)(bn + row) * K + k0 + c8;
            cp16(Bs + row * GKP + c8, sb, 16);
        }
    };

    const int nT = K / 64;
    load_stage(0, 0);
    CP_COMMIT();
    for (int i = 0; i < nT; i++) {
        CP_WAIT0();
        __syncthreads();
        if (i + 1 < nT) { load_stage((i + 1) & 1, (i + 1) * 64); CP_COMMIT(); }
        const __half* As = gsm + (i & 1) * GSTG;
        const __half* Bs = As + 128 * GKP;
#pragma unroll
        for (int ks = 0; ks < 4; ks++) {
            int kk = ks * 16;
            uint32_t af[4][4], bf[4][2];
#pragma unroll
            for (int mt = 0; mt < 4; mt++) {
                const __half* p = As + (wm * 64 + mt * 16) * GKP + kk + 2 * t;
                af[mt][0] = *(const uint32_t*)(p + (g    ) * GKP);
                af[mt][1] = *(const uint32_t*)(p + (g + 8) * GKP);
                af[mt][2] = *(const uint32_t*)(p + (g    ) * GKP + 8);
                af[mt][3] = *(const uint32_t*)(p + (g + 8) * GKP + 8);
            }
#pragma unroll
            for (int nt = 0; nt < 4; nt++) {
                const __half* p = Bs + (wn * 32 + nt * 8 + g) * GKP + kk + 2 * t;
                bf[nt][0] = *(const uint32_t*)(p);
                bf[nt][1] = *(const uint32_t*)(p + 8);
            }
#pragma unroll
            for (int mt = 0; mt < 4; mt++)
#pragma unroll
                for (int nt = 0; nt < 4; nt++)
                    mma_f16(acc[mt][nt], af[mt][0], af[mt][1], af[mt][2], af[mt][3],
                            bf[nt][0], bf[nt][1]);
        }
        __syncthreads();
    }
    const int seg = bn / DIM;
    const int colbase = bn - seg * DIM;
    const float* bias = bqkv + seg * DIM;
#pragma unroll
    for (int mt = 0; mt < 4; mt++) {
#pragma unroll
        for (int nt = 0; nt < 4; nt++) {
            int col = colbase + wn * 32 + nt * 8 + 2 * t;
            float2 b2 = *(const float2*)(bias + col);
            int r0 = bm + wm * 64 + mt * 16 + g;
            int r1 = r0 + 8;
            float v00 = acc[mt][nt][0] + b2.x, v01 = acc[mt][nt][1] + b2.y;
            float v10 = acc[mt][nt][2] + b2.x, v11 = acc[mt][nt][3] + b2.y;
            if (seg == 2) {
                if (r0 < M) *(uint32_t*)(Vo + (size_t)r0 * DIM + col) = pack_h2(v00, v01);
                if (r1 < M) *(uint32_t*)(Vo + (size_t)r1 * DIM + col) = pack_h2(v10, v11);
            } else {
                float* C = (seg == 0) ? Qo : Ko;
                if (r0 < M) *(float2*)(C + (size_t)r0 * DIM + col) = make_float2(v00, v01);
                if (r1 < M) *(float2*)(C + (size_t)r1 * DIM + col) = make_float2(v10, v11);
            }
        }
    }
}

// ---------------- out projection GEMM ----------------
__global__ __launch_bounds__(256, 2) void gemm_async_kernel(
    const __half* __restrict__ A, const __half* __restrict__ W,
    const float* __restrict__ bias, float* __restrict__ C,
    int M, int N, int K) {
    extern __shared__ __half gsm[];
    const int tid = threadIdx.x;
    const int warp = tid >> 5, lane = tid & 31;
    const int g = lane >> 2, t = lane & 3;
    const int wm = warp >> 2, wn = warp & 3;
    const int bm = blockIdx.y * 128, bn = blockIdx.x * 128;

    float acc[4][4][4];
#pragma unroll
    for (int i = 0; i < 4; i++)
#pragma unroll
        for (int j = 0; j < 4; j++)
#pragma unroll
            for (int r = 0; r < 4; r++) acc[i][j][r] = 0.f;

    auto load_stage = [&](int s, int k0) {
        __half* As = gsm + s * GSTG;
        __half* Bs = As + 128 * GKP;
#pragma unroll
        for (int it = 0; it < 4; it++) {
            int f = it * 256 + tid;
            int row = f >> 3, c8 = (f & 7) * 8;
            int gm = bm + row;
            const __half* sa = A + (size_t)(gm < M ? gm : M - 1) * K + k0 + c8;
            cp16(As + row * GKP + c8, sa, gm < M ? 16 : 0);
            const __half* sb = W + (size_t)(bn + row) * K + k0 + c8;
            cp16(Bs + row * GKP + c8, sb, 16);
        }
    };

    const int nT = K / 64;
    load_stage(0, 0);
    CP_COMMIT();
    for (int i = 0; i < nT; i++) {
        CP_WAIT0();
        __syncthreads();
        if (i + 1 < nT) { load_stage((i + 1) & 1, (i + 1) * 64); CP_COMMIT(); }
        const __half* As = gsm + (i & 1) * GSTG;
        const __half* Bs = As + 128 * GKP;
#pragma unroll
        for (int ks = 0; ks < 4; ks++) {
            int kk = ks * 16;
            uint32_t af[4][4], bf[4][2];
#pragma unroll
            for (int mt = 0; mt < 4; mt++) {
                const __half* p = As + (wm * 64 + mt * 16) * GKP + kk + 2 * t;
                af[mt][0] = *(const uint32_t*)(p + (g    ) * GKP);
                af[mt][1] = *(const uint32_t*)(p + (g + 8) * GKP);
                af[mt][2] = *(const uint32_t*)(p + (g    ) * GKP + 8);
                af[mt][3] = *(const uint32_t*)(p + (g + 8) * GKP + 8);
            }
#pragma unroll
            for (int nt = 0; nt < 4; nt++) {
                const __half* p = Bs + (wn * 32 + nt * 8 + g) * GKP + kk + 2 * t;
                bf[nt][0] = *(const uint32_t*)(p);
                bf[nt][1] = *(const uint32_t*)(p + 8);
            }
#pragma unroll
            for (int mt = 0; mt < 4; mt++)
#pragma unroll
                for (int nt = 0; nt < 4; nt++)
                    mma_f16(acc[mt][nt], af[mt][0], af[mt][1], af[mt][2], af[mt][3],
                            bf[nt][0], bf[nt][1]);
        }
        __syncthreads();
    }
#pragma unroll
    for (int mt = 0; mt < 4; mt++) {
#pragma unroll
        for (int nt = 0; nt < 4; nt++) {
            int col = bn + wn * 32 + nt * 8 + 2 * t;
            float2 b2 = *(const float2*)(bias + col);
            int r0 = bm + wm * 64 + mt * 16 + g;
            int r1 = r0 + 8;
            if (r0 < M)
                *(float2*)(C + (size_t)r0 * N + col) =
                    make_float2(acc[mt][nt][0] + b2.x, acc[mt][nt][1] + b2.y);
            if (r1 < M)
                *(float2*)(C + (size_t)r1 * N + col) =
                    make_float2(acc[mt][nt][2] + b2.x, acc[mt][nt][3] + b2.y);
        }
    }
}

// ---------------- fused rmsnorm (+z) + rope -> fp16; blockIdx.y: 0=Q(z) 1=K ----------------
__global__ __launch_bounds__(384) void qkpost_kernel(
    const float* __restrict__ Qf, const float* __restrict__ Kf,
    const float* __restrict__ gq, const float* __restrict__ gk,
    const float* __restrict__ gkm, const float* __restrict__ freqs,
    __half* __restrict__ RQh, __half* __restrict__ RKh, float* __restrict__ Z) {
    __shared__ float vals[DIM];
    __shared__ float red[12];
    __shared__ float s_scale;
    const bool isQ = (blockIdx.y == 0);
    const float* X  = isQ ? Qf : Kf;
    const float* gw = isQ ? gq : gk;
    __half* Yh      = isQ ? RQh : RKh;
    const int s = blockIdx.x;
    const int tid = threadIdx.x;
    const int lane = tid & 31, wid = tid >> 5;
    const float* x = X + (size_t)s * DIM;

    float ss = 0.f;
#pragma unroll
    for (int k = 0; k < 4; k++) {
        int i = tid + k * 384;
        float v = x[i];
        vals[i] = v;
        ss += v * v;
    }
#pragma unroll
    for (int o = 16; o > 0; o >>= 1) ss += __shfl_xor_sync(0xffffffffu, ss, o);
    if (lane == 0) red[wid] = ss;
    __syncthreads();
    if (wid == 0) {
        float v = (lane < 12) ? red[lane] : 0.f;
#pragma unroll
        for (int o = 8; o > 0; o >>= 1) v += __shfl_xor_sync(0xffffffffu, v, o);
        if (lane == 0) s_scale = rsqrtf(v / (float)DIM + 1e-6f);
    }
    __syncthreads();
    const float sc = s_scale;
#pragma unroll
    for (int k = 0; k < 4; k++) {
        int i = tid + k * 384;
        vals[i] = vals[i] * sc * gw[i];
    }
    __syncthreads();
    if (isQ) {
        const float* vh = vals + wid * HD;
        float sum = 0.f;
#pragma unroll
        for (int k = 0; k < 4; k++) {
            int d = lane + k * 32;
            sum += fmaxf(vh[d], 0.f) * gkm[wid * HD + d];
        }
#pragma unroll
        for (int o = 16; o > 0; o >>= 1) sum += __shfl_xor_sync(0xffffffffu, sum, o);
        if (lane == 0) Z[s * NH + wid] = 1.f / (sum + 1e-6f);
    }
    const int w = s % 52, h = (s / 52) % 30, f = s / (52 * 30);
#pragma unroll
    for (int k = 0; k < 2; k++) {
        int p = tid + k * 384;
        int i = p & 63;
        int pos = (i < 22) ? f : (i < 43) ? h : w;
        float cr = freqs[(pos * 64 + i) * 2 + 0];
        float ci = freqs[(pos * 64 + i) * 2 + 1];
        float xr = vals[2 * p], xi = vals[2 * p + 1];
        *(uint32_t*)(Yh + (size_t)s * DIM + 2 * p) =
            pack_h2(xr * cr - xi * ci, xr * ci + xi * cr);
    }
}

// ---------------- Wlin transpose ----------------
__global__ void transpose128_kernel(const float* __restrict__ in, float* __restrict__ out) {
    int j = blockIdx.x, m = threadIdx.x;
    out[m * HD + j] = in[j * HD + m];
}

// ---------------- G2h[n][j][d] ----------------
__global__ void g2_kernel(const float* __restrict__ gkv, const float* __restrict__ WT,
                          __half* __restrict__ G2h) {
    int nd = blockIdx.x;
    int n = nd >> 7, d = nd & 127;
    __shared__ float kv[HD];
    kv[threadIdx.x] = gkv[(size_t)nd * HD + threadIdx.x];
    __syncthreads();
    int j = threadIdx.x;
    float sum = 0.f;
#pragma unroll 8
    for (int m = 0; m < HD; m++) sum += kv[m] * WT[m * HD + j];
    G2h[((size_t)n * HD + j) * HD + d] = __float2half(sum);
}

// ---------------- FP16 flash attention (base-2 softmax, pre-scaled Q) + fused xg ----------------
#define KPH 136
#define ASTG (2 * 128 * KPH)
#define ATT_SMEM (2 * ASTG * 2)
__global__ __launch_bounds__(256, 1) void attn_h_kernel(
    const __half* __restrict__ RQh, const __half* __restrict__ RKh,
    const __half* __restrict__ Vh, const __half* __restrict__ G2h,
    const float* __restrict__ Z, const float* __restrict__ blin,
    __half* __restrict__ XLh) {
    extern __shared__ __half smh[];
    const int tid = threadIdx.x;
    const int warp = tid >> 5, lane = tid & 31;
    const int g = lane >> 2, t = lane & 3;
    const int head = blockIdx.y;
    const int q0 = blockIdx.x * 128;

    // stage Q scaled by QSCALE (base-2 softmax fold)
    {
        __half* Qs = smh;
        const __half2 qs2 = __float2half2_rn(QSCALE);
#pragma unroll
        for (int it = 0; it < 8; it++) {
            int f = it * 256 + tid;
            int row = f >> 4, c8 = (f & 15) * 8;
            int s = q0 + row;
            uint4 v = make_uint4(0, 0, 0, 0);
            if (s < S_LEN) v = *(const uint4*)(RQh + ((size_t)s * NH + head) * HD + c8);
            __half2* hv = (__half2*)&v;
            hv[0] = __hmul2(hv[0], qs2);
            hv[1] = __hmul2(hv[1], qs2);
            hv[2] = __hmul2(hv[2], qs2);
            hv[3] = __hmul2(hv[3], qs2);
            *(uint4*)&Qs[row * KPH + c8] = v;
        }
    }
    __syncthreads();
    uint32_t qf[8][4];
    {
        const __half* p = smh + (warp * 16) * KPH + 2 * t;
#pragma unroll
        for (int kt = 0; kt < 8; kt++) {
            int kk = kt * 16;
            qf[kt][0] = *(const uint32_t*)(p + (g    ) * KPH + kk);
            qf[kt][1] = *(const uint32_t*)(p + (g + 8) * KPH + kk);
            qf[kt][2] = *(const uint32_t*)(p + (g    ) * KPH + kk + 8);
            qf[kt][3] = *(const uint32_t*)(p + (g + 8) * KPH + kk + 8);
        }
    }
    __syncthreads();

    auto load_kv = [&](int st, int k0) {
        __half* Ks = smh + st * ASTG;
        __half* Vs = Ks + 128 * KPH;
#pragma unroll
        for (int it = 0; it < 8; it++) {
            int f = it * 256 + tid;
            int row = f >> 4, c8 = (f & 15) * 8;
            int s = k0 + row;
            int sb = (s < S_LEN) ? 16 : 0;
            size_t off = ((size_t)(s < S_LEN ? s : S_LEN - 1) * NH + head) * HD + c8;
            cp16(Ks + row * KPH + c8, RKh + off, sb);
            cp16(Vs + row * KPH + c8, Vh + off, sb);
        }
    };

    float o_acc[16][4];
#pragma unroll
    for (int nt = 0; nt < 16; nt++)
#pragma unroll
        for (int r = 0; r < 4; r++) o_acc[nt][r] = 0.f;
    float m0 = -1e30f, m1 = -1e30f, l0 = 0.f, l1 = 0.f;
    const int T = (S_LEN + 127) / 128;

    float sf[16][4];
    load_kv(0, 0);
    CP_COMMIT();
    for (int ti = 0; ti < T; ti++) {
        CP_WAIT0();
        __syncthreads();
        if (ti + 1 < T) { load_kv((ti + 1) & 1, (ti + 1) * 128); CP_COMMIT(); }
        const __half* Ks = smh + (ti & 1) * ASTG;
        const __half* Vs = Ks + 128 * KPH;
        const int k0 = ti * 128;

#pragma unroll
        for (int nt = 0; nt < 16; nt++)
#pragma unroll
            for (int r = 0; r < 4; r++) sf[nt][r] = 0.f;
#pragma unroll
        for (int kt = 0; kt < 8; kt++) {
            int kk = kt * 16 + 2 * t;
#pragma unroll
            for (int nt = 0; nt < 16; nt++) {
                const __half* p = Ks + (nt * 8 + g) * KPH + kk;
                uint32_t b0 = *(const uint32_t*)(p);
                uint32_t b1 = *(const uint32_t*)(p + 8);
                mma_f16(sf[nt], qf[kt][0], qf[kt][1], qf[kt][2], qf[kt][3], b0, b1);
            }
        }
        // scores already scaled; mask tail only
        if (k0 + 128 > S_LEN) {
#pragma unroll
            for (int nt = 0; nt < 16; nt++) {
                int col = k0 + nt * 8 + 2 * t;
                if (col     >= S_LEN) { sf[nt][0] = -1e30f; sf[nt][2] = -1e30f; }
                if (col + 1 >= S_LEN) { sf[nt][1] = -1e30f; sf[nt][3] = -1e30f; }
            }
        }
        float mx0 = -1e30f, mx1 = -1e30f;
#pragma unroll
        for (int nt = 0; nt < 16; nt++) {
            mx0 = fmaxf(mx0, fmaxf(sf[nt][0], sf[nt][1]));
            mx1 = fmaxf(mx1, fmaxf(sf[nt][2], sf[nt][3]));
        }
        mx0 = fmaxf(mx0, __shfl_xor_sync(0xffffffffu, mx0, 1));
        mx0 = fmaxf(mx0, __shfl_xor_sync(0xffffffffu, mx0, 2));
        mx1 = fmaxf(mx1, __shfl_xor_sync(0xffffffffu, mx1, 1));
        mx1 = fmaxf(mx1, __shfl_xor_sync(0xffffffffu, mx1, 2));
        float mn0 = fmaxf(m0, mx0), mn1 = fmaxf(m1, mx1);
        float c0 = ex2f(m0 - mn0), c1 = ex2f(m1 - mn1);
        float s0 = 0.f, s1 = 0.f;
#pragma unroll
        for (int nt = 0; nt < 16; nt++) {
            sf[nt][0] = ex2f(sf[nt][0] - mn0);
            sf[nt][1] = ex2f(sf[nt][1] - mn0);
            sf[nt][2] = ex2f(sf[nt][2] - mn1);
            sf[nt][3] = ex2f(sf[nt][3] - mn1);
            s0 += sf[nt][0] + sf[nt][1];
            s1 += sf[nt][2] + sf[nt][3];
        }
        s0 += __shfl_xor_sync(0xffffffffu, s0, 1);
        s0 += __shfl_xor_sync(0xffffffffu, s0, 2);
        s1 += __shfl_xor_sync(0xffffffffu, s1, 1);
        s1 += __shfl_xor_sync(0xffffffffu, s1, 2);
        l0 = l0 * c0 + s0;  l1 = l1 * c1 + s1;
        m0 = mn0;  m1 = mn1;
#pragma unroll
        for (int nt = 0; nt < 16; nt++) {
            o_acc[nt][0] *= c0; o_acc[nt][1] *= c0;
            o_acc[nt][2] *= c1; o_acc[nt][3] *= c1;
        }
        const int vr = lane & 7, vq = lane >> 3;
#pragma unroll
        for (int kt = 0; kt < 8; kt++) {
            uint32_t a0 = pack_h2(sf[2*kt  ][0], sf[2*kt  ][1]);
            uint32_t a1 = pack_h2(sf[2*kt  ][2], sf[2*kt  ][3]);
            uint32_t a2 = pack_h2(sf[2*kt+1][0], sf[2*kt+1][1]);
            uint32_t a3 = pack_h2(sf[2*kt+1][2], sf[2*kt+1][3]);
#pragma unroll
            for (int nb = 0; nb < 8; nb++) {
                const __half* vp = Vs + (kt * 16 + (vq & 1) * 8 + vr) * KPH
                                      + nb * 16 + (vq >> 1) * 8;
                uint32_t v0, v1, v2, v3;
                ldmx4t(v0, v1, v2, v3, vp);
                mma_f16(o_acc[2*nb    ], a0, a1, a2, a3, v0, v1);
                mma_f16(o_acc[2*nb + 1], a0, a1, a2, a3, v2, v3);
            }
        }
        __syncthreads();
    }

    // ---- fused xg (qf is pre-scaled by QSCALE; compensate via z) ----
    {
        __half* G2s = smh;
#pragma unroll
        for (int it = 0; it < 8; it++) {
            int f = it * 256 + tid;
            int row = f >> 4, c8 = (f & 15) * 8;
            uint4 gv = *(const uint4*)(G2h + ((size_t)head * HD + row) * HD + c8);
            *(uint4*)&G2s[row * KPH + c8] = gv;
        }
        __syncthreads();
#pragma unroll
        for (int nt = 0; nt < 16; nt++)
#pragma unroll
            for (int r = 0; r < 4; r++) sf[nt][r] = 0.f;
#pragma unroll
        for (int kt = 0; kt < 8; kt++) {
            int kk = kt * 16 + 2 * t;
#pragma unroll
            for (int nt = 0; nt < 16; nt++) {
                const __half* p = G2s + (nt * 8 + g) * KPH + kk;
                uint32_t b0 = *(const uint32_t*)(p);
                uint32_t b1 = *(const uint32_t*)(p + 8);
                mma_f16(sf[nt], qf[kt][0], qf[kt][1], qf[kt][2], qf[kt][3], b0, b1);
            }
        }
    }

    float inv0 = 1.f / l0, inv1 = 1.f / l1;
    int s0r = q0 + warp * 16 + g;
    int s1r = s0r + 8;
    float z0 = (s0r < S_LEN) ? Z[s0r * NH + head] * INV_QSCALE : 0.f;
    float z1 = (s1r < S_LEN) ? Z[s1r * NH + head] * INV_QSCALE : 0.f;
#pragma unroll
    for (int nt = 0; nt < 16; nt++) {
        int col = nt * 8 + 2 * t;
        float2 bl = *(const float2*)(blin + col);
        if (s0r < S_LEN) {
            float v0 = o_acc[nt][0] * inv0 + sf[nt][0] * z0 + bl.x;
            float v1 = o_acc[nt][1] * inv0 + sf[nt][1] * z0 + bl.y;
            *(uint32_t*)(XLh + ((size_t)s0r * NH + head) * HD + col) = pack_h2(v0, v1);
        }
        if (s1r < S_LEN) {
            float v0 = o_acc[nt][2] * inv1 + sf[nt][2] * z1 + bl.x;
            float v1 = o_acc[nt][3] * inv1 + sf[nt][3] * z1 + bl.y;
            *(uint32_t*)(XLh + ((size_t)s1r * NH + head) * HD + col) = pack_h2(v0, v1);
        }
    }
}

// ---------------- launch ----------------
extern "C" void kernel_launch(void* const* d_in, const int* in_sizes, int n_in,
                              void* d_out, int out_size) {
    const float* x    = (const float*)d_in[0];
    const float* freqs= (const float*)d_in[1];
    const float* gkm  = (const float*)d_in[2];
    const float* gkv  = (const float*)d_in[3];
    const float* Wq   = (const float*)d_in[4];
    const float* bq   = (const float*)d_in[5];
    const float* Wk   = (const float*)d_in[6];
    const float* bk   = (const float*)d_in[7];
    const float* Wv   = (const float*)d_in[8];
    const float* bv   = (const float*)d_in[9];
    const float* Wo   = (const float*)d_in[10];
    const float* bo   = (const float*)d_in[11];
    const float* gq   = (const float*)d_in[12];
    const float* gk   = (const float*)d_in[13];
    const float* Wlin = (const float*)d_in[14];
    const float* blin = (const float*)d_in[15];
    float* out = (float*)d_out;

    float *Qp, *Kp, *Zp, *WTp, *bqkv;
    __half *xh, *Wqkvh, *Woh, *Vh, *RQh, *RKh, *XLh, *G2h;
    cudaGetSymbolAddress((void**)&Qp,   g_Q);
    cudaGetSymbolAddress((void**)&Kp,   g_K);
    cudaGetSymbolAddress((void**)&Zp,   g_Z);
    cudaGetSymbolAddress((void**)&WTp,  g_WT);
    cudaGetSymbolAddress((void**)&bqkv, g_bqkv);
    cudaGetSymbolAddress((void**)&xh,   g_xh);
    cudaGetSymbolAddress((void**)&Wqkvh,g_Wqkvh);
    cudaGetSymbolAddress((void**)&Woh,  g_Woh);
    cudaGetSymbolAddress((void**)&Vh,   g_Vh);
    cudaGetSymbolAddress((void**)&RQh,  g_RQh);
    cudaGetSymbolAddress((void**)&RKh,  g_RKh);
    cudaGetSymbolAddress((void**)&XLh,  g_XLh);
    cudaGetSymbolAddress((void**)&G2h,  g_G2h);

    cudaFuncSetAttribute(gemm_qkv_kernel,   cudaFuncAttributeMaxDynamicSharedMemorySize, GEMM_SMEM);
    cudaFuncSetAttribute(gemm_async_kernel, cudaFuncAttributeMaxDynamicSharedMemorySize, GEMM_SMEM);
    cudaFuncSetAttribute(attn_h_kernel, cudaFuncAttributeMaxDynamicSharedMemorySize, ATT_SMEM);

    f2h_all_kernel<<<1024, 256>>>(x, Wq, Wk, Wv, Wo, bq, bk, bv, xh, Wqkvh, Woh, bqkv);
    {
        dim3 grid(3 * DIM / 128, (S_LEN + 127) / 128);
        gemm_qkv_kernel<<<grid, 256, GEMM_SMEM>>>(xh, Wqkvh, bqkv, Qp, Kp, Vh);
    }
    {
        dim3 grid(S_LEN, 2);
        qkpost_kernel<<<grid, 384>>>(Qp, Kp, gq, gk, gkm, freqs, RQh, RKh, Zp);
    }
    transpose128_kernel<<<HD, HD>>>(Wlin, WTp);
    g2_kernel<<<NH * HD, HD>>>(gkv, WTp, G2h);
    {
        dim3 grid((S_LEN + 127) / 128, NH);
        attn_h_kernel<<<grid, 256, ATT_SMEM>>>(RQh, RKh, Vh, G2h, Zp, blin, XLh);
    }
    {
        dim3 grid(DIM / 128, (S_LEN + 127) / 128);
        gemm_async_kernel<<<grid, 256, GEMM_SMEM>>>(XLh, Woh, bo, out, S_LEN, DIM, DIM);
    }
}